// round 2
// baseline (speedup 1.0000x reference)
#include <cuda_runtime.h>
#include <math.h>

#define BB   16
#define NN   512
#define DD   512
#define HH   8
#define KTOP 16
#define HD   64
#define MSL  512
#define ROWS (BB*NN)     // 8192
#define DFF  2048

// ---------------- scratch (static device memory; no allocs allowed) ----------
__device__ float g_xn   [ROWS*DD];
__device__ float g_q    [ROWS*DD];
__device__ float g_k    [ROWS*DD];
__device__ float g_v    [ROWS*DD];
__device__ float g_logits[(size_t)BB*HH*NN*NN];   // 134 MB
__device__ float g_attn [ROWS*DD];
__device__ float g_x1   [ROWS*DD];
__device__ float g_xn2  [ROWS*DD];
__device__ float g_ff   [(size_t)ROWS*DFF];

// ---------------- LayerNorm: one block (256 thr) per row of 512 --------------
__global__ void __launch_bounds__(256) ln_kernel(
    const float* __restrict__ x, const float* __restrict__ g,
    const float* __restrict__ be, float* __restrict__ out)
{
    int row = blockIdx.x;
    const float* xr = x + (size_t)row * DD;
    int t = threadIdx.x;
    float v0 = xr[t], v1 = xr[t + 256];
    float s = v0 + v1, ss = v0 * v0 + v1 * v1;
    #pragma unroll
    for (int o = 16; o; o >>= 1) {
        s  += __shfl_xor_sync(0xFFFFFFFFu, s,  o);
        ss += __shfl_xor_sync(0xFFFFFFFFu, ss, o);
    }
    __shared__ float red0[8], red1[8];
    __shared__ float smean, srstd;
    int wid = t >> 5, lane = t & 31;
    if (lane == 0) { red0[wid] = s; red1[wid] = ss; }
    __syncthreads();
    if (t == 0) {
        float a = 0.f, b2 = 0.f;
        #pragma unroll
        for (int i = 0; i < 8; i++) { a += red0[i]; b2 += red1[i]; }
        float mean = a * (1.0f / DD);
        float var  = b2 * (1.0f / DD) - mean * mean;
        smean = mean;
        srstd = rsqrtf(var + 1e-5f);
    }
    __syncthreads();
    float m = smean, r = srstd;
    out[(size_t)row * DD + t]       = (v0 - m) * r * g[t]       + be[t];
    out[(size_t)row * DD + t + 256] = (v1 - m) * r * g[t + 256] + be[t + 256];
}

// ---------------- classic 128x128x8 fp32 SGEMM, fused bias/gelu/residual -----
template<bool GELU, bool RES>
__global__ void __launch_bounds__(256) sgemm(
    const float* __restrict__ A, const float* __restrict__ B,
    const float* __restrict__ bias, const float* __restrict__ res,
    float* __restrict__ C, int M, int N, int K)
{
    __shared__ float As[8][128];
    __shared__ float Bs[8][128];
    int tid = threadIdx.x;
    int n0 = blockIdx.x * 128, m0 = blockIdx.y * 128;
    const float* Ap = A + (size_t)m0 * K;
    const float* Bp = B + n0;
    int arow = tid >> 1, acol = (tid & 1) * 4;
    int brow = tid >> 5, bcol = (tid & 31) * 4;
    int tx = tid & 15, ty = tid >> 4;

    float acc[8][8];
    #pragma unroll
    for (int i = 0; i < 8; i++)
        #pragma unroll
        for (int j = 0; j < 8; j++) acc[i][j] = 0.f;

    for (int k0 = 0; k0 < K; k0 += 8) {
        float4 a = *(const float4*)(Ap + (size_t)arow * K + k0 + acol);
        float4 b = *(const float4*)(Bp + (size_t)(k0 + brow) * N + bcol);
        As[acol + 0][arow] = a.x;
        As[acol + 1][arow] = a.y;
        As[acol + 2][arow] = a.z;
        As[acol + 3][arow] = a.w;
        *(float4*)&Bs[brow][bcol] = b;
        __syncthreads();
        #pragma unroll
        for (int kk = 0; kk < 8; kk++) {
            float4 a0 = *(float4*)&As[kk][ty * 8];
            float4 a1 = *(float4*)&As[kk][ty * 8 + 4];
            float4 b0 = *(float4*)&Bs[kk][tx * 8];
            float4 b1 = *(float4*)&Bs[kk][tx * 8 + 4];
            float ar[8] = {a0.x, a0.y, a0.z, a0.w, a1.x, a1.y, a1.z, a1.w};
            float br[8] = {b0.x, b0.y, b0.z, b0.w, b1.x, b1.y, b1.z, b1.w};
            #pragma unroll
            for (int i = 0; i < 8; i++)
                #pragma unroll
                for (int j = 0; j < 8; j++)
                    acc[i][j] += ar[i] * br[j];
        }
        __syncthreads();
    }

    #pragma unroll
    for (int i = 0; i < 8; i++) {
        int row = m0 + ty * 8 + i;
        #pragma unroll
        for (int j4 = 0; j4 < 8; j4 += 4) {
            float4 o;
            float* po = (float*)&o;
            #pragma unroll
            for (int j = 0; j < 4; j++) {
                int col = n0 + tx * 8 + j4 + j;
                float val = acc[i][j4 + j] + bias[col];
                if (GELU) val = 0.5f * val * (1.0f + erff(val * 0.70710678118654752f));
                if (RES)  val += res[(size_t)row * N + col];
                po[j] = val;
            }
            *(float4*)(C + (size_t)row * N + n0 + tx * 8 + j4) = o;
        }
    }
}

// ---------------- logits = scale * Q K^T + rel bias, per (b,h), 64x64 tiles --
__global__ void __launch_bounds__(256) logits_kernel(
    const float* __restrict__ q, const float* __restrict__ k,
    const float* __restrict__ rel, float* __restrict__ logits)
{
    __shared__ float Qs[64][68];
    __shared__ float Ks[64][68];
    int bh = blockIdx.z;
    int b = bh >> 3, h = bh & 7;
    int nt = blockIdx.x * 64, mt = blockIdx.y * 64;
    const float* qp = q + ((size_t)(b * NN + nt)) * DD + h * HD;
    const float* kp = k + ((size_t)(b * NN + mt)) * DD + h * HD;
    int tid = threadIdx.x;

    #pragma unroll
    for (int r = 0; r < 4; r++) {
        int idx = tid + 256 * r;
        int row = idx >> 4, d4 = (idx & 15) * 4;
        float4 qv = *(const float4*)(qp + (size_t)row * DD + d4);
        Qs[d4 + 0][row] = qv.x; Qs[d4 + 1][row] = qv.y;
        Qs[d4 + 2][row] = qv.z; Qs[d4 + 3][row] = qv.w;
        float4 kv = *(const float4*)(kp + (size_t)row * DD + d4);
        Ks[d4 + 0][row] = kv.x; Ks[d4 + 1][row] = kv.y;
        Ks[d4 + 2][row] = kv.z; Ks[d4 + 3][row] = kv.w;
    }
    __syncthreads();

    int tx = tid & 15, ty = tid >> 4;
    float acc[4][4];
    #pragma unroll
    for (int i = 0; i < 4; i++)
        #pragma unroll
        for (int j = 0; j < 4; j++) acc[i][j] = 0.f;

    #pragma unroll
    for (int d = 0; d < 64; d++) {
        float4 qv = *(float4*)&Qs[d][ty * 4];
        float4 kv = *(float4*)&Ks[d][tx * 4];
        float qr[4] = {qv.x, qv.y, qv.z, qv.w};
        float kr[4] = {kv.x, kv.y, kv.z, kv.w};
        #pragma unroll
        for (int i = 0; i < 4; i++)
            #pragma unroll
            for (int j = 0; j < 4; j++)
                acc[i][j] += qr[i] * kr[j];
    }

    #pragma unroll
    for (int i = 0; i < 4; i++) {
        int n = nt + ty * 4 + i;
        int mbase = mt + tx * 4;
        float4 o;
        o.x = acc[i][0] * 0.125f + rel[(mbase + 0 - n + MSL - 1) * HH + h];
        o.y = acc[i][1] * 0.125f + rel[(mbase + 1 - n + MSL - 1) * HH + h];
        o.z = acc[i][2] * 0.125f + rel[(mbase + 2 - n + MSL - 1) * HH + h];
        o.w = acc[i][3] * 0.125f + rel[(mbase + 3 - n + MSL - 1) * HH + h];
        *(float4*)(logits + ((size_t)bh * NN + n) * NN + mbase) = o;
    }
}

// ---------------- top-16 + softmax + sparse A*V: one warp per (b,h,n) row ----
__global__ void __launch_bounds__(256) topk_kernel(
    const float* __restrict__ logits, const float* __restrict__ v,
    float* __restrict__ attn)
{
    int w = (blockIdx.x * blockDim.x + threadIdx.x) >> 5;   // row id, 0..65535
    int lane = threadIdx.x & 31;
    int n = w & (NN - 1);
    int h = (w >> 9) & 7;
    int b = w >> 12;

    const float* lrow = logits + (size_t)w * NN;
    float vals[16];
    #pragma unroll
    for (int t = 0; t < 16; t++) vals[t] = lrow[t * 32 + lane];

    unsigned mask = 0xFFFFu;
    float selv = 0.f;
    int   selm = 0;
    #pragma unroll
    for (int r = 0; r < 16; r++) {
        float bv = -INFINITY; int bs = 0;
        #pragma unroll
        for (int t = 0; t < 16; t++) {
            bool live = (mask >> t) & 1u;
            if (live && vals[t] > bv) { bv = vals[t]; bs = t; }
        }
        float rv = bv;
        int rm = bs * 32 + lane;
        #pragma unroll
        for (int off = 16; off; off >>= 1) {
            float ov = __shfl_xor_sync(0xFFFFFFFFu, rv, off);
            int   om = __shfl_xor_sync(0xFFFFFFFFu, rm, off);
            if (ov > rv || (ov == rv && om < rm)) { rv = ov; rm = om; }
        }
        if ((rm & 31) == lane) mask &= ~(1u << (rm >> 5));
        if (lane == r) { selv = rv; selm = rm; }
    }

    // softmax over 16 selections (held by lanes 0..15, descending)
    float maxv = __shfl_sync(0xFFFFFFFFu, selv, 0);
    float e = (lane < 16) ? expf(selv - maxv) : 0.f;
    float s = e;
    #pragma unroll
    for (int off = 16; off; off >>= 1) s += __shfl_xor_sync(0xFFFFFFFFu, s, off);
    float p = e / s;

    // out[d] = sum_l p_l * V[b, m_l, h, d]
    float o0 = 0.f, o1 = 0.f;
    const float* vbase = v + ((size_t)b * NN) * DD + h * HD;
    #pragma unroll
    for (int l = 0; l < 16; l++) {
        float pl = __shfl_sync(0xFFFFFFFFu, p, l);
        int   ml = __shfl_sync(0xFFFFFFFFu, selm, l);
        const float* vr = vbase + (size_t)ml * DD;
        o0 += pl * vr[lane];
        o1 += pl * vr[lane + 32];
    }
    float* dst = attn + ((size_t)(b * NN + n)) * DD + h * HD;
    dst[lane]      = o0;
    dst[lane + 32] = o1;
}

// ---------------------------------------------------------------------------
extern "C" void kernel_launch(void* const* d_in, const int* in_sizes, int n_in,
                              void* d_out, int out_size)
{
    const float* x   = (const float*)d_in[0];
    const float* wq  = (const float*)d_in[1];
    const float* bq  = (const float*)d_in[2];
    const float* wk  = (const float*)d_in[3];
    const float* bk  = (const float*)d_in[4];
    const float* wv  = (const float*)d_in[5];
    const float* bv  = (const float*)d_in[6];
    const float* wo  = (const float*)d_in[7];
    const float* bo  = (const float*)d_in[8];
    const float* g1  = (const float*)d_in[9];
    const float* be1 = (const float*)d_in[10];
    const float* g2  = (const float*)d_in[11];
    const float* be2 = (const float*)d_in[12];
    const float* w1  = (const float*)d_in[13];
    const float* bf1 = (const float*)d_in[14];
    const float* w2  = (const float*)d_in[15];
    const float* bf2 = (const float*)d_in[16];
    const float* rel = (const float*)d_in[17];
    float* out = (float*)d_out;

    float *xn, *q, *k, *v, *logits, *attn, *x1, *xn2, *ff;
    cudaGetSymbolAddress((void**)&xn,     g_xn);
    cudaGetSymbolAddress((void**)&q,      g_q);
    cudaGetSymbolAddress((void**)&k,      g_k);
    cudaGetSymbolAddress((void**)&v,      g_v);
    cudaGetSymbolAddress((void**)&logits, g_logits);
    cudaGetSymbolAddress((void**)&attn,   g_attn);
    cudaGetSymbolAddress((void**)&x1,     g_x1);
    cudaGetSymbolAddress((void**)&xn2,    g_xn2);
    cudaGetSymbolAddress((void**)&ff,     g_ff);

    dim3 gD(DD / 128, ROWS / 128);      // 4 x 64
    dim3 gF(DFF / 128, ROWS / 128);     // 16 x 64

    // 1. LN1
    ln_kernel<<<ROWS, 256>>>(x, g1, be1, xn);
    // 2. Q,K,V projections
    sgemm<false, false><<<gD, 256>>>(xn, wq, bq, nullptr, q, ROWS, DD, DD);
    sgemm<false, false><<<gD, 256>>>(xn, wk, bk, nullptr, k, ROWS, DD, DD);
    sgemm<false, false><<<gD, 256>>>(xn, wv, bv, nullptr, v, ROWS, DD, DD);
    // 3. logits + relative bias
    logits_kernel<<<dim3(NN / 64, NN / 64, BB * HH), 256>>>(q, k, rel, logits);
    // 4. top-16 -> softmax -> sparse A*V
    topk_kernel<<<(BB * HH * NN * 32) / 256, 256>>>(logits, v, attn);
    // 5. output projection + residual
    sgemm<false, true><<<gD, 256>>>(attn, wo, bo, x, x1, ROWS, DD, DD);
    // 6. LN2
    ln_kernel<<<ROWS, 256>>>(x1, g2, be2, xn2);
    // 7. FFN up + exact GELU
    sgemm<true, false><<<gF, 256>>>(xn2, w1, bf1, nullptr, ff, ROWS, DFF, DD);
    // 8. FFN down + residual -> output
    sgemm<false, true><<<gD, 256>>>(ff, w2, bf2, x1, out, ROWS, DD, DFF);
}

// round 6
// speedup vs baseline: 1.7994x; 1.7994x over previous
#include <cuda_runtime.h>
#include <cuda_bf16.h>
#include <math.h>
#include <stdint.h>

#define BB   16
#define NN   512
#define DD   512
#define HH   8
#define KTOP 16
#define HD   64
#define MSL  512
#define ROWS (BB*NN)     // 8192
#define DFF  2048

// ---------------- scratch (static device memory; no allocs allowed) ----------
__device__ float g_q    [ROWS*DD];
__device__ float g_k    [ROWS*DD];
__device__ float g_v    [ROWS*DD];
__device__ float g_logits[(size_t)BB*HH*NN*NN];   // 134 MB
__device__ float g_x1   [ROWS*DD];

__device__ __nv_bfloat16 g_xnb_h  [ROWS*DD];
__device__ __nv_bfloat16 g_xnb_l  [ROWS*DD];
__device__ __nv_bfloat16 g_xn2b_h [ROWS*DD];
__device__ __nv_bfloat16 g_xn2b_l [ROWS*DD];
__device__ __nv_bfloat16 g_attnb_h[ROWS*DD];
__device__ __nv_bfloat16 g_attnb_l[ROWS*DD];
__device__ __nv_bfloat16 g_ffb_h  [(size_t)ROWS*DFF];
__device__ __nv_bfloat16 g_ffb_l  [(size_t)ROWS*DFF];
__device__ __nv_bfloat16 g_wtq_h  [DD*DD];
__device__ __nv_bfloat16 g_wtq_l  [DD*DD];
__device__ __nv_bfloat16 g_wtk_h  [DD*DD];
__device__ __nv_bfloat16 g_wtk_l  [DD*DD];
__device__ __nv_bfloat16 g_wtv_h  [DD*DD];
__device__ __nv_bfloat16 g_wtv_l  [DD*DD];
__device__ __nv_bfloat16 g_wto_h  [DD*DD];
__device__ __nv_bfloat16 g_wto_l  [DD*DD];
__device__ __nv_bfloat16 g_wt1_h  [(size_t)DD*DFF];
__device__ __nv_bfloat16 g_wt1_l  [(size_t)DD*DFF];
__device__ __nv_bfloat16 g_wt2_h  [(size_t)DFF*DD];
__device__ __nv_bfloat16 g_wt2_l  [(size_t)DFF*DD];

// ================= PTX helpers (base sm_103 target legal) ====================
__device__ __forceinline__ uint32_t smem_u32(const void* p) {
    uint32_t a;
    asm("{ .reg .u64 t; cvta.to.shared.u64 t, %1; cvt.u32.u64 %0, t; }" : "=r"(a) : "l"(p));
    return a;
}
__device__ __forceinline__ void cpa16(uint32_t dst, const void* src) {
    asm volatile("cp.async.cg.shared.global [%0], [%1], 16;" :: "r"(dst), "l"(src));
}
__device__ __forceinline__ void cpa_commit() {
    asm volatile("cp.async.commit_group;" ::: "memory");
}
template<int N>
__device__ __forceinline__ void cpa_wait() {
    asm volatile("cp.async.wait_group %0;" :: "n"(N) : "memory");
}
__device__ __forceinline__ void ldsm4(uint32_t* r, uint32_t addr) {
    asm volatile("ldmatrix.sync.aligned.m8n8.x4.shared.b16 {%0,%1,%2,%3}, [%4];"
                 : "=r"(r[0]), "=r"(r[1]), "=r"(r[2]), "=r"(r[3]) : "r"(addr));
}
__device__ __forceinline__ void mma16816(float* c, const uint32_t* a, const uint32_t* b) {
    asm volatile(
        "mma.sync.aligned.m16n8k16.row.col.f32.bf16.bf16.f32 "
        "{%0,%1,%2,%3}, {%4,%5,%6,%7}, {%8,%9}, {%0,%1,%2,%3};"
        : "+f"(c[0]), "+f"(c[1]), "+f"(c[2]), "+f"(c[3])
        : "r"(a[0]), "r"(a[1]), "r"(a[2]), "r"(a[3]), "r"(b[0]), "r"(b[1]));
}

// ================= bf16x3 HMMA GEMM (fp32-accurate): 128x128 tile ===========
// Inputs: hi/lo bf16 pairs. acc += Ah*Bh + Al*Bh + Ah*Bl  (Al*Bl ~ eps^2, dropped)
// MODE 0: C(fp32) = acc + bias
// MODE 1: C(fp32) = acc + bias + res
// MODE 2: hi/lo bf16 = gelu(acc + bias)
#define LDA 40                         // padded smem row (elements)
#define TILEB (128 * LDA * 2)          // 10240 bytes per tile
#define BUFB  (4 * TILEB)              // Ah,Al,Bh,Bl per buffer

template<int MODE>
__global__ void __launch_bounds__(256, 2) gemm_mma(
    const __nv_bfloat16* __restrict__ Ah, const __nv_bfloat16* __restrict__ Al,
    const __nv_bfloat16* __restrict__ Bh, const __nv_bfloat16* __restrict__ Bl,
    const float* __restrict__ bias, const float* __restrict__ res,
    void* __restrict__ Cout, void* __restrict__ Cout2, int M, int N, int Kd)
{
    extern __shared__ char smem[];
    uint32_t sbase = smem_u32(smem);

    int tid = threadIdx.x, wid = tid >> 5, lane = tid & 31;
    int n0 = blockIdx.x * 128, m0 = blockIdx.y * 128;
    int wr = wid & 3, wc = wid >> 2;   // warp: 32 M-rows x 64 N-cols

    const __nv_bfloat16* Aph = Ah + (size_t)m0 * Kd;
    const __nv_bfloat16* Apl = Al + (size_t)m0 * Kd;
    const __nv_bfloat16* Bph = Bh + (size_t)n0 * Kd;
    const __nv_bfloat16* Bpl = Bl + (size_t)n0 * Kd;

    float acc[2][8][4];
    #pragma unroll
    for (int i = 0; i < 2; i++)
        #pragma unroll
        for (int j = 0; j < 8; j++)
            #pragma unroll
            for (int q = 0; q < 4; q++) acc[i][j][q] = 0.f;

    // per-thread stage-load indices: each tile is 512 16B-chunks / 256 thr = 2 each
    int r0 = tid >> 2, c0 = (tid & 3) * 8;
    int r1 = r0 + 64;
    uint32_t off0 = (uint32_t)(r0 * LDA + c0) * 2;
    uint32_t off1 = (uint32_t)(r1 * LDA + c0) * 2;

    auto load_stage = [&](int s, int buf) {
        int k0 = s * 32;
        uint32_t b = sbase + buf * BUFB;
        cpa16(b             + off0, Aph + (size_t)r0 * Kd + k0 + c0);
        cpa16(b             + off1, Aph + (size_t)r1 * Kd + k0 + c0);
        cpa16(b + TILEB     + off0, Apl + (size_t)r0 * Kd + k0 + c0);
        cpa16(b + TILEB     + off1, Apl + (size_t)r1 * Kd + k0 + c0);
        cpa16(b + 2 * TILEB + off0, Bph + (size_t)r0 * Kd + k0 + c0);
        cpa16(b + 2 * TILEB + off1, Bph + (size_t)r1 * Kd + k0 + c0);
        cpa16(b + 3 * TILEB + off0, Bpl + (size_t)r0 * Kd + k0 + c0);
        cpa16(b + 3 * TILEB + off1, Bpl + (size_t)r1 * Kd + k0 + c0);
    };

    int S = Kd >> 5;
    load_stage(0, 0);
    cpa_commit();

    // fragment addresses (tile-relative, constant per thread)
    uint32_t a_off[2], b_off[4];
    #pragma unroll
    for (int mt = 0; mt < 2; mt++) {
        int row = wr * 32 + mt * 16 + (lane & 15);
        a_off[mt] = (uint32_t)(row * LDA + (lane >> 4) * 8) * 2;
    }
    #pragma unroll
    for (int nt = 0; nt < 4; nt++) {
        int nrow = wc * 64 + nt * 16 + (lane & 7) + ((lane >> 4) & 1) * 8;
        b_off[nt] = (uint32_t)(nrow * LDA + ((lane >> 3) & 1) * 8) * 2;
    }

    for (int s = 0; s < S; s++) {
        int buf = s & 1;
        if (s + 1 < S) { load_stage(s + 1, buf ^ 1); cpa_commit(); cpa_wait<1>(); }
        else          { cpa_wait<0>(); }
        __syncthreads();

        uint32_t ah = sbase + buf * BUFB;
        uint32_t al = ah + TILEB;
        uint32_t bh = ah + 2 * TILEB;
        uint32_t bl = ah + 3 * TILEB;
        #pragma unroll
        for (int kk = 0; kk < 2; kk++) {
            uint32_t afh[2][4], afl[2][4];
            #pragma unroll
            for (int mt = 0; mt < 2; mt++) {
                ldsm4(afh[mt], ah + a_off[mt] + kk * 32);
                ldsm4(afl[mt], al + a_off[mt] + kk * 32);
            }
            #pragma unroll
            for (int nt = 0; nt < 4; nt++) {
                uint32_t bfh[4], bfl[4];
                ldsm4(bfh, bh + b_off[nt] + kk * 32);
                ldsm4(bfl, bl + b_off[nt] + kk * 32);
                #pragma unroll
                for (int mt = 0; mt < 2; mt++) {
                    mma16816(acc[mt][nt * 2 + 0], afh[mt], bfh + 0);
                    mma16816(acc[mt][nt * 2 + 1], afh[mt], bfh + 2);
                    mma16816(acc[mt][nt * 2 + 0], afl[mt], bfh + 0);
                    mma16816(acc[mt][nt * 2 + 1], afl[mt], bfh + 2);
                    mma16816(acc[mt][nt * 2 + 0], afh[mt], bfl + 0);
                    mma16816(acc[mt][nt * 2 + 1], afh[mt], bfl + 2);
                }
            }
        }
        __syncthreads();
    }

    // epilogue: c-frag rows = gr (+8), cols = tg*2 (+1)
    int gr = lane >> 2, tg = lane & 3;
    #pragma unroll
    for (int mt = 0; mt < 2; mt++) {
        int rbase = m0 + wr * 32 + mt * 16 + gr;
        #pragma unroll
        for (int j = 0; j < 8; j++) {
            int col = n0 + wc * 64 + j * 8 + tg * 2;
            #pragma unroll
            for (int half = 0; half < 2; half++) {
                int row = rbase + half * 8;
                float v0 = acc[mt][j][half * 2 + 0] + bias[col];
                float v1 = acc[mt][j][half * 2 + 1] + bias[col + 1];
                if (MODE == 2) {
                    v0 = 0.5f * v0 * (1.0f + erff(v0 * 0.70710678118654752f));
                    v1 = 0.5f * v1 * (1.0f + erff(v1 * 0.70710678118654752f));
                    __nv_bfloat162 ph, pl;
                    ph.x = __float2bfloat16(v0);
                    ph.y = __float2bfloat16(v1);
                    pl.x = __float2bfloat16(v0 - __bfloat162float(ph.x));
                    pl.y = __float2bfloat16(v1 - __bfloat162float(ph.y));
                    *(__nv_bfloat162*)((__nv_bfloat16*)Cout  + (size_t)row * N + col) = ph;
                    *(__nv_bfloat162*)((__nv_bfloat16*)Cout2 + (size_t)row * N + col) = pl;
                } else {
                    if (MODE == 1) {
                        const float* rr = res + (size_t)row * N + col;
                        v0 += rr[0]; v1 += rr[1];
                    }
                    float2 o; o.x = v0; o.y = v1;
                    *(float2*)((float*)Cout + (size_t)row * N + col) = o;
                }
            }
        }
    }
}

// ---------------- weight transpose + fp32 -> bf16 hi/lo ---------------------
__global__ void __launch_bounds__(256) wconv(
    const float* __restrict__ w, __nv_bfloat16* __restrict__ wth,
    __nv_bfloat16* __restrict__ wtl, int Kd, int Nd)
{
    __shared__ float t[32][33];
    int k0 = blockIdx.x * 32, n0 = blockIdx.y * 32;
    int tx = threadIdx.x & 31, ty = threadIdx.x >> 5;   // 32 x 8
    #pragma unroll
    for (int i = 0; i < 4; i++)
        t[ty + 8 * i][tx] = w[(size_t)(k0 + ty + 8 * i) * Nd + n0 + tx];
    __syncthreads();
    #pragma unroll
    for (int i = 0; i < 4; i++) {
        float v = t[tx][ty + 8 * i];
        __nv_bfloat16 h = __float2bfloat16(v);
        size_t o = (size_t)(n0 + ty + 8 * i) * Kd + k0 + tx;
        wth[o] = h;
        wtl[o] = __float2bfloat16(v - __bfloat162float(h));
    }
}

// ---------------- LayerNorm -> bf16 hi/lo ------------------------------------
__global__ void __launch_bounds__(256) ln_kernel(
    const float* __restrict__ x, const float* __restrict__ g,
    const float* __restrict__ be, __nv_bfloat16* __restrict__ oh,
    __nv_bfloat16* __restrict__ ol)
{
    int row = blockIdx.x;
    const float* xr = x + (size_t)row * DD;
    int t = threadIdx.x;
    float v0 = xr[t], v1 = xr[t + 256];
    float s = v0 + v1, ss = v0 * v0 + v1 * v1;
    #pragma unroll
    for (int o = 16; o; o >>= 1) {
        s  += __shfl_xor_sync(0xFFFFFFFFu, s,  o);
        ss += __shfl_xor_sync(0xFFFFFFFFu, ss, o);
    }
    __shared__ float red0[8], red1[8];
    __shared__ float smean, srstd;
    int wid = t >> 5, lane = t & 31;
    if (lane == 0) { red0[wid] = s; red1[wid] = ss; }
    __syncthreads();
    if (t == 0) {
        float a = 0.f, b2 = 0.f;
        #pragma unroll
        for (int i = 0; i < 8; i++) { a += red0[i]; b2 += red1[i]; }
        float mean = a * (1.0f / DD);
        float var  = b2 * (1.0f / DD) - mean * mean;
        smean = mean;
        srstd = rsqrtf(var + 1e-5f);
    }
    __syncthreads();
    float m = smean, r = srstd;
    float y0 = (v0 - m) * r * g[t]       + be[t];
    float y1 = (v1 - m) * r * g[t + 256] + be[t + 256];
    __nv_bfloat16 h0 = __float2bfloat16(y0);
    __nv_bfloat16 h1 = __float2bfloat16(y1);
    size_t o0 = (size_t)row * DD + t;
    oh[o0]       = h0;
    oh[o0 + 256] = h1;
    ol[o0]       = __float2bfloat16(y0 - __bfloat162float(h0));
    ol[o0 + 256] = __float2bfloat16(y1 - __bfloat162float(h1));
}

// ---------------- logits = scale * Q K^T + rel bias (fp32) ------------------
__global__ void __launch_bounds__(256) logits_kernel(
    const float* __restrict__ q, const float* __restrict__ k,
    const float* __restrict__ rel, float* __restrict__ logits)
{
    __shared__ float Qs[64][68];
    __shared__ float Ks[64][68];
    int bh = blockIdx.z;
    int b = bh >> 3, h = bh & 7;
    int nt = blockIdx.x * 64, mt = blockIdx.y * 64;
    const float* qp = q + ((size_t)(b * NN + nt)) * DD + h * HD;
    const float* kp = k + ((size_t)(b * NN + mt)) * DD + h * HD;
    int tid = threadIdx.x;

    #pragma unroll
    for (int r = 0; r < 4; r++) {
        int idx = tid + 256 * r;
        int row = idx >> 4, d4 = (idx & 15) * 4;
        float4 qv = *(const float4*)(qp + (size_t)row * DD + d4);
        Qs[d4 + 0][row] = qv.x; Qs[d4 + 1][row] = qv.y;
        Qs[d4 + 2][row] = qv.z; Qs[d4 + 3][row] = qv.w;
        float4 kv = *(const float4*)(kp + (size_t)row * DD + d4);
        Ks[d4 + 0][row] = kv.x; Ks[d4 + 1][row] = kv.y;
        Ks[d4 + 2][row] = kv.z; Ks[d4 + 3][row] = kv.w;
    }
    __syncthreads();

    int tx = tid & 15, ty = tid >> 4;
    float acc[4][4];
    #pragma unroll
    for (int i = 0; i < 4; i++)
        #pragma unroll
        for (int j = 0; j < 4; j++) acc[i][j] = 0.f;

    #pragma unroll
    for (int d = 0; d < 64; d++) {
        float4 qv = *(float4*)&Qs[d][ty * 4];
        float4 kv = *(float4*)&Ks[d][tx * 4];
        float qr[4] = {qv.x, qv.y, qv.z, qv.w};
        float kr[4] = {kv.x, kv.y, kv.z, kv.w};
        #pragma unroll
        for (int i = 0; i < 4; i++)
            #pragma unroll
            for (int j = 0; j < 4; j++)
                acc[i][j] += qr[i] * kr[j];
    }

    #pragma unroll
    for (int i = 0; i < 4; i++) {
        int n = nt + ty * 4 + i;
        int mbase = mt + tx * 4;
        float4 o;
        o.x = acc[i][0] * 0.125f + rel[(mbase + 0 - n + MSL - 1) * HH + h];
        o.y = acc[i][1] * 0.125f + rel[(mbase + 1 - n + MSL - 1) * HH + h];
        o.z = acc[i][2] * 0.125f + rel[(mbase + 2 - n + MSL - 1) * HH + h];
        o.w = acc[i][3] * 0.125f + rel[(mbase + 3 - n + MSL - 1) * HH + h];
        *(float4*)(logits + ((size_t)bh * NN + n) * NN + mbase) = o;
    }
}

// ---------------- top-16 + softmax + sparse A*V -> bf16 hi/lo ---------------
__global__ void __launch_bounds__(256) topk_kernel(
    const float* __restrict__ logits, const float* __restrict__ v,
    __nv_bfloat16* __restrict__ ah, __nv_bfloat16* __restrict__ al)
{
    int w = (blockIdx.x * blockDim.x + threadIdx.x) >> 5;   // row id, 0..65535
    int lane = threadIdx.x & 31;
    int n = w & (NN - 1);
    int h = (w >> 9) & 7;
    int b = w >> 12;

    const float* lrow = logits + (size_t)w * NN;
    float vals[16];
    #pragma unroll
    for (int t = 0; t < 16; t++) vals[t] = lrow[t * 32 + lane];

    unsigned mask = 0xFFFFu;
    float selv = 0.f;
    int   selm = 0;
    #pragma unroll
    for (int r = 0; r < 16; r++) {
        float bv = -INFINITY; int bs = 0;
        #pragma unroll
        for (int t = 0; t < 16; t++) {
            bool live = (mask >> t) & 1u;
            if (live && vals[t] > bv) { bv = vals[t]; bs = t; }
        }
        float rv = bv;
        int rm = bs * 32 + lane;
        #pragma unroll
        for (int off = 16; off; off >>= 1) {
            float ov = __shfl_xor_sync(0xFFFFFFFFu, rv, off);
            int   om = __shfl_xor_sync(0xFFFFFFFFu, rm, off);
            if (ov > rv || (ov == rv && om < rm)) { rv = ov; rm = om; }
        }
        if ((rm & 31) == lane) mask &= ~(1u << (rm >> 5));
        if (lane == r) { selv = rv; selm = rm; }
    }

    float maxv = __shfl_sync(0xFFFFFFFFu, selv, 0);
    float e = (lane < 16) ? expf(selv - maxv) : 0.f;
    float s = e;
    #pragma unroll
    for (int off = 16; off; off >>= 1) s += __shfl_xor_sync(0xFFFFFFFFu, s, off);
    float p = e / s;

    float o0 = 0.f, o1 = 0.f;
    const float* vbase = v + ((size_t)b * NN) * DD + h * HD;
    #pragma unroll
    for (int l = 0; l < 16; l++) {
        float pl = __shfl_sync(0xFFFFFFFFu, p, l);
        int   ml = __shfl_sync(0xFFFFFFFFu, selm, l);
        const float* vr = vbase + (size_t)ml * DD;
        o0 += pl * vr[lane];
        o1 += pl * vr[lane + 32];
    }
    size_t base = ((size_t)(b * NN + n)) * DD + h * HD;
    __nv_bfloat16 h0 = __float2bfloat16(o0);
    __nv_bfloat16 h1 = __float2bfloat16(o1);
    ah[base + lane]      = h0;
    ah[base + lane + 32] = h1;
    al[base + lane]      = __float2bfloat16(o0 - __bfloat162float(h0));
    al[base + lane + 32] = __float2bfloat16(o1 - __bfloat162float(h1));
}

// ---------------------------------------------------------------------------
extern "C" void kernel_launch(void* const* d_in, const int* in_sizes, int n_in,
                              void* d_out, int out_size)
{
    const float* x   = (const float*)d_in[0];
    const float* wq  = (const float*)d_in[1];
    const float* bq  = (const float*)d_in[2];
    const float* wk  = (const float*)d_in[3];
    const float* bk  = (const float*)d_in[4];
    const float* wv  = (const float*)d_in[5];
    const float* bv  = (const float*)d_in[6];
    const float* wo  = (const float*)d_in[7];
    const float* bo  = (const float*)d_in[8];
    const float* g1  = (const float*)d_in[9];
    const float* be1 = (const float*)d_in[10];
    const float* g2  = (const float*)d_in[11];
    const float* be2 = (const float*)d_in[12];
    const float* w1  = (const float*)d_in[13];
    const float* bf1 = (const float*)d_in[14];
    const float* w2  = (const float*)d_in[15];
    const float* bf2 = (const float*)d_in[16];
    const float* rel = (const float*)d_in[17];
    float* out = (float*)d_out;

    float *q, *k, *v, *logits, *x1;
    __nv_bfloat16 *xnh, *xnl, *xn2h, *xn2l, *ath, *atl, *ffh, *ffl;
    __nv_bfloat16 *wqh, *wql, *wkh, *wkl, *wvh, *wvl, *woh, *wol, *w1h, *w1l, *w2h, *w2l;
    cudaGetSymbolAddress((void**)&q,      g_q);
    cudaGetSymbolAddress((void**)&k,      g_k);
    cudaGetSymbolAddress((void**)&v,      g_v);
    cudaGetSymbolAddress((void**)&logits, g_logits);
    cudaGetSymbolAddress((void**)&x1,     g_x1);
    cudaGetSymbolAddress((void**)&xnh,    g_xnb_h);
    cudaGetSymbolAddress((void**)&xnl,    g_xnb_l);
    cudaGetSymbolAddress((void**)&xn2h,   g_xn2b_h);
    cudaGetSymbolAddress((void**)&xn2l,   g_xn2b_l);
    cudaGetSymbolAddress((void**)&ath,    g_attnb_h);
    cudaGetSymbolAddress((void**)&atl,    g_attnb_l);
    cudaGetSymbolAddress((void**)&ffh,    g_ffb_h);
    cudaGetSymbolAddress((void**)&ffl,    g_ffb_l);
    cudaGetSymbolAddress((void**)&wqh,    g_wtq_h);
    cudaGetSymbolAddress((void**)&wql,    g_wtq_l);
    cudaGetSymbolAddress((void**)&wkh,    g_wtk_h);
    cudaGetSymbolAddress((void**)&wkl,    g_wtk_l);
    cudaGetSymbolAddress((void**)&wvh,    g_wtv_h);
    cudaGetSymbolAddress((void**)&wvl,    g_wtv_l);
    cudaGetSymbolAddress((void**)&woh,    g_wto_h);
    cudaGetSymbolAddress((void**)&wol,    g_wto_l);
    cudaGetSymbolAddress((void**)&w1h,    g_wt1_h);
    cudaGetSymbolAddress((void**)&w1l,    g_wt1_l);
    cudaGetSymbolAddress((void**)&w2h,    g_wt2_h);
    cudaGetSymbolAddress((void**)&w2l,    g_wt2_l);

    const int SMEM_GEMM = 2 * BUFB;   // 81920
    cudaFuncSetAttribute(gemm_mma<0>, cudaFuncAttributeMaxDynamicSharedMemorySize, SMEM_GEMM);
    cudaFuncSetAttribute(gemm_mma<1>, cudaFuncAttributeMaxDynamicSharedMemorySize, SMEM_GEMM);
    cudaFuncSetAttribute(gemm_mma<2>, cudaFuncAttributeMaxDynamicSharedMemorySize, SMEM_GEMM);

    // weight transpose + hi/lo convert
    wconv<<<dim3(DD / 32, DD / 32),  256>>>(wq, wqh, wql, DD, DD);
    wconv<<<dim3(DD / 32, DD / 32),  256>>>(wk, wkh, wkl, DD, DD);
    wconv<<<dim3(DD / 32, DD / 32),  256>>>(wv, wvh, wvl, DD, DD);
    wconv<<<dim3(DD / 32, DD / 32),  256>>>(wo, woh, wol, DD, DD);
    wconv<<<dim3(DD / 32, DFF / 32), 256>>>(w1, w1h, w1l, DD, DFF);
    wconv<<<dim3(DFF / 32, DD / 32), 256>>>(w2, w2h, w2l, DFF, DD);

    dim3 gD(DD / 128, ROWS / 128);      // 4 x 64
    dim3 gF(DFF / 128, ROWS / 128);     // 16 x 64

    // 1. LN1 -> bf16 hi/lo
    ln_kernel<<<ROWS, 256>>>(x, g1, be1, xnh, xnl);
    // 2. Q,K,V projections (bf16x3 HMMA, fp32-accurate)
    gemm_mma<0><<<gD, 256, SMEM_GEMM>>>(xnh, xnl, wqh, wql, bq, nullptr, q, nullptr, ROWS, DD, DD);
    gemm_mma<0><<<gD, 256, SMEM_GEMM>>>(xnh, xnl, wkh, wkl, bk, nullptr, k, nullptr, ROWS, DD, DD);
    gemm_mma<0><<<gD, 256, SMEM_GEMM>>>(xnh, xnl, wvh, wvl, bv, nullptr, v, nullptr, ROWS, DD, DD);
    // 3. logits + relative bias (fp32)
    logits_kernel<<<dim3(NN / 64, NN / 64, BB * HH), 256>>>(q, k, rel, logits);
    // 4. top-16 -> softmax -> sparse A*V -> bf16 hi/lo
    topk_kernel<<<(BB * HH * NN * 32) / 256, 256>>>(logits, v, ath, atl);
    // 5. output projection + residual
    gemm_mma<1><<<gD, 256, SMEM_GEMM>>>(ath, atl, woh, wol, bo, x, x1, nullptr, ROWS, DD, DD);
    // 6. LN2 -> bf16 hi/lo
    ln_kernel<<<ROWS, 256>>>(x1, g2, be2, xn2h, xn2l);
    // 7. FFN up + exact GELU -> bf16 hi/lo
    gemm_mma<2><<<gF, 256, SMEM_GEMM>>>(xn2h, xn2l, w1h, w1l, bf1, nullptr, ffh, ffl, ROWS, DFF, DD);
    // 8. FFN down + residual -> output
    gemm_mma<1><<<gD, 256, SMEM_GEMM>>>(ffh, ffl, w2h, w2l, bf2, x1, out, nullptr, ROWS, DD, DFF);
}

// round 7
// speedup vs baseline: 2.0600x; 1.1448x over previous
#include <cuda_runtime.h>
#include <cuda_bf16.h>
#include <math.h>
#include <stdint.h>

#define BB   16
#define NN   512
#define DD   512
#define HH   8
#define KTOP 16
#define HD   64
#define MSL  512
#define ROWS (BB*NN)     // 8192
#define DFF  2048

// ---------------- scratch (static device memory; no allocs allowed) ----------
__device__ float g_v    [ROWS*DD];
__device__ float g_logits[(size_t)BB*HH*NN*NN];   // 134 MB
__device__ float g_x1   [ROWS*DD];

__device__ __nv_bfloat16 g_qb_h  [ROWS*DD];
__device__ __nv_bfloat16 g_qb_l  [ROWS*DD];
__device__ __nv_bfloat16 g_kb_h  [ROWS*DD];
__device__ __nv_bfloat16 g_kb_l  [ROWS*DD];
__device__ __nv_bfloat16 g_xnb_h  [ROWS*DD];
__device__ __nv_bfloat16 g_xnb_l  [ROWS*DD];
__device__ __nv_bfloat16 g_xn2b_h [ROWS*DD];
__device__ __nv_bfloat16 g_xn2b_l [ROWS*DD];
__device__ __nv_bfloat16 g_attnb_h[ROWS*DD];
__device__ __nv_bfloat16 g_attnb_l[ROWS*DD];
__device__ __nv_bfloat16 g_ffb_h  [(size_t)ROWS*DFF];
__device__ __nv_bfloat16 g_ffb_l  [(size_t)ROWS*DFF];
__device__ __nv_bfloat16 g_wtq_h  [DD*DD];
__device__ __nv_bfloat16 g_wtq_l  [DD*DD];
__device__ __nv_bfloat16 g_wtk_h  [DD*DD];
__device__ __nv_bfloat16 g_wtk_l  [DD*DD];
__device__ __nv_bfloat16 g_wtv_h  [DD*DD];
__device__ __nv_bfloat16 g_wtv_l  [DD*DD];
__device__ __nv_bfloat16 g_wto_h  [DD*DD];
__device__ __nv_bfloat16 g_wto_l  [DD*DD];
__device__ __nv_bfloat16 g_wt1_h  [(size_t)DD*DFF];
__device__ __nv_bfloat16 g_wt1_l  [(size_t)DD*DFF];
__device__ __nv_bfloat16 g_wt2_h  [(size_t)DFF*DD];
__device__ __nv_bfloat16 g_wt2_l  [(size_t)DFF*DD];

// ================= PTX helpers (base sm_103 target legal) ====================
__device__ __forceinline__ uint32_t smem_u32(const void* p) {
    uint32_t a;
    asm("{ .reg .u64 t; cvta.to.shared.u64 t, %1; cvt.u32.u64 %0, t; }" : "=r"(a) : "l"(p));
    return a;
}
__device__ __forceinline__ void cpa16(uint32_t dst, const void* src) {
    asm volatile("cp.async.cg.shared.global [%0], [%1], 16;" :: "r"(dst), "l"(src));
}
__device__ __forceinline__ void cpa_commit() {
    asm volatile("cp.async.commit_group;" ::: "memory");
}
template<int N>
__device__ __forceinline__ void cpa_wait() {
    asm volatile("cp.async.wait_group %0;" :: "n"(N) : "memory");
}
__device__ __forceinline__ void ldsm4(uint32_t* r, uint32_t addr) {
    asm volatile("ldmatrix.sync.aligned.m8n8.x4.shared.b16 {%0,%1,%2,%3}, [%4];"
                 : "=r"(r[0]), "=r"(r[1]), "=r"(r[2]), "=r"(r[3]) : "r"(addr));
}
__device__ __forceinline__ void mma16816(float* c, const uint32_t* a, const uint32_t* b) {
    asm volatile(
        "mma.sync.aligned.m16n8k16.row.col.f32.bf16.bf16.f32 "
        "{%0,%1,%2,%3}, {%4,%5,%6,%7}, {%8,%9}, {%0,%1,%2,%3};"
        : "+f"(c[0]), "+f"(c[1]), "+f"(c[2]), "+f"(c[3])
        : "r"(a[0]), "r"(a[1]), "r"(a[2]), "r"(a[3]), "r"(b[0]), "r"(b[1]));
}

// ================= bf16x3 HMMA GEMM (fp32-accurate): 128x128 tile ===========
// acc += Ah*Bh + Al*Bh + Ah*Bl   (Al*Bl ~ eps^2, dropped)
// MODE 0: C(fp32) = acc + bias
// MODE 1: C(fp32) = acc + bias + res
// MODE 2: hi/lo bf16 = gelu(acc + bias)
// MODE 3: hi/lo bf16 = acc + bias
#define LDA 40                         // padded smem row (elements)
#define TILEB (128 * LDA * 2)          // 10240 bytes per tile
#define BUFB  (4 * TILEB)              // Ah,Al,Bh,Bl per buffer

template<int MODE>
__global__ void __launch_bounds__(256, 2) gemm_mma(
    const __nv_bfloat16* __restrict__ Ah, const __nv_bfloat16* __restrict__ Al,
    const __nv_bfloat16* __restrict__ Bh, const __nv_bfloat16* __restrict__ Bl,
    const float* __restrict__ bias, const float* __restrict__ res,
    void* __restrict__ Cout, void* __restrict__ Cout2, int M, int N, int Kd)
{
    extern __shared__ char smem[];
    uint32_t sbase = smem_u32(smem);

    int tid = threadIdx.x, wid = tid >> 5, lane = tid & 31;
    int n0 = blockIdx.x * 128, m0 = blockIdx.y * 128;
    int wr = wid & 3, wc = wid >> 2;   // warp: 32 M-rows x 64 N-cols

    const __nv_bfloat16* Aph = Ah + (size_t)m0 * Kd;
    const __nv_bfloat16* Apl = Al + (size_t)m0 * Kd;
    const __nv_bfloat16* Bph = Bh + (size_t)n0 * Kd;
    const __nv_bfloat16* Bpl = Bl + (size_t)n0 * Kd;

    float acc[2][8][4];
    #pragma unroll
    for (int i = 0; i < 2; i++)
        #pragma unroll
        for (int j = 0; j < 8; j++)
            #pragma unroll
            for (int q = 0; q < 4; q++) acc[i][j][q] = 0.f;

    int r0 = tid >> 2, c0 = (tid & 3) * 8;
    int r1 = r0 + 64;
    uint32_t off0 = (uint32_t)(r0 * LDA + c0) * 2;
    uint32_t off1 = (uint32_t)(r1 * LDA + c0) * 2;

    auto load_stage = [&](int s, int buf) {
        int k0 = s * 32;
        uint32_t b = sbase + buf * BUFB;
        cpa16(b             + off0, Aph + (size_t)r0 * Kd + k0 + c0);
        cpa16(b             + off1, Aph + (size_t)r1 * Kd + k0 + c0);
        cpa16(b + TILEB     + off0, Apl + (size_t)r0 * Kd + k0 + c0);
        cpa16(b + TILEB     + off1, Apl + (size_t)r1 * Kd + k0 + c0);
        cpa16(b + 2 * TILEB + off0, Bph + (size_t)r0 * Kd + k0 + c0);
        cpa16(b + 2 * TILEB + off1, Bph + (size_t)r1 * Kd + k0 + c0);
        cpa16(b + 3 * TILEB + off0, Bpl + (size_t)r0 * Kd + k0 + c0);
        cpa16(b + 3 * TILEB + off1, Bpl + (size_t)r1 * Kd + k0 + c0);
    };

    int S = Kd >> 5;
    load_stage(0, 0);
    cpa_commit();

    uint32_t a_off[2], b_off[4];
    #pragma unroll
    for (int mt = 0; mt < 2; mt++) {
        int row = wr * 32 + mt * 16 + (lane & 15);
        a_off[mt] = (uint32_t)(row * LDA + (lane >> 4) * 8) * 2;
    }
    #pragma unroll
    for (int nt = 0; nt < 4; nt++) {
        int nrow = wc * 64 + nt * 16 + (lane & 7) + ((lane >> 4) & 1) * 8;
        b_off[nt] = (uint32_t)(nrow * LDA + ((lane >> 3) & 1) * 8) * 2;
    }

    for (int s = 0; s < S; s++) {
        int buf = s & 1;
        if (s + 1 < S) { load_stage(s + 1, buf ^ 1); cpa_commit(); cpa_wait<1>(); }
        else          { cpa_wait<0>(); }
        __syncthreads();

        uint32_t ah = sbase + buf * BUFB;
        uint32_t al = ah + TILEB;
        uint32_t bh = ah + 2 * TILEB;
        uint32_t bl = ah + 3 * TILEB;
        #pragma unroll
        for (int kk = 0; kk < 2; kk++) {
            uint32_t afh[2][4], afl[2][4];
            #pragma unroll
            for (int mt = 0; mt < 2; mt++) {
                ldsm4(afh[mt], ah + a_off[mt] + kk * 32);
                ldsm4(afl[mt], al + a_off[mt] + kk * 32);
            }
            #pragma unroll
            for (int nt = 0; nt < 4; nt++) {
                uint32_t bfh[4], bfl[4];
                ldsm4(bfh, bh + b_off[nt] + kk * 32);
                ldsm4(bfl, bl + b_off[nt] + kk * 32);
                #pragma unroll
                for (int mt = 0; mt < 2; mt++) {
                    mma16816(acc[mt][nt * 2 + 0], afh[mt], bfh + 0);
                    mma16816(acc[mt][nt * 2 + 1], afh[mt], bfh + 2);
                    mma16816(acc[mt][nt * 2 + 0], afl[mt], bfh + 0);
                    mma16816(acc[mt][nt * 2 + 1], afl[mt], bfh + 2);
                    mma16816(acc[mt][nt * 2 + 0], afh[mt], bfl + 0);
                    mma16816(acc[mt][nt * 2 + 1], afh[mt], bfl + 2);
                }
            }
        }
        __syncthreads();
    }

    int gr = lane >> 2, tg = lane & 3;
    #pragma unroll
    for (int mt = 0; mt < 2; mt++) {
        int rbase = m0 + wr * 32 + mt * 16 + gr;
        #pragma unroll
        for (int j = 0; j < 8; j++) {
            int col = n0 + wc * 64 + j * 8 + tg * 2;
            #pragma unroll
            for (int half = 0; half < 2; half++) {
                int row = rbase + half * 8;
                float v0 = acc[mt][j][half * 2 + 0] + bias[col];
                float v1 = acc[mt][j][half * 2 + 1] + bias[col + 1];
                if (MODE == 2 || MODE == 3) {
                    if (MODE == 2) {
                        v0 = 0.5f * v0 * (1.0f + erff(v0 * 0.70710678118654752f));
                        v1 = 0.5f * v1 * (1.0f + erff(v1 * 0.70710678118654752f));
                    }
                    __nv_bfloat162 ph, pl;
                    ph.x = __float2bfloat16(v0);
                    ph.y = __float2bfloat16(v1);
                    pl.x = __float2bfloat16(v0 - __bfloat162float(ph.x));
                    pl.y = __float2bfloat16(v1 - __bfloat162float(ph.y));
                    *(__nv_bfloat162*)((__nv_bfloat16*)Cout  + (size_t)row * N + col) = ph;
                    *(__nv_bfloat162*)((__nv_bfloat16*)Cout2 + (size_t)row * N + col) = pl;
                } else {
                    if (MODE == 1) {
                        const float* rr = res + (size_t)row * N + col;
                        v0 += rr[0]; v1 += rr[1];
                    }
                    float2 o; o.x = v0; o.y = v1;
                    *(float2*)((float*)Cout + (size_t)row * N + col) = o;
                }
            }
        }
    }
}

// ============ logits: bf16x3 HMMA, per (b,h), 128x128 tile, Kd=64 ===========
__global__ void __launch_bounds__(256, 2) logits_mma(
    const __nv_bfloat16* __restrict__ Qh, const __nv_bfloat16* __restrict__ Ql,
    const __nv_bfloat16* __restrict__ Kh, const __nv_bfloat16* __restrict__ Kl,
    const float* __restrict__ rel, float* __restrict__ logits)
{
    extern __shared__ char smem[];
    uint32_t sbase = smem_u32(smem);

    int tid = threadIdx.x, wid = tid >> 5, lane = tid & 31;
    int bh = blockIdx.z;
    int b = bh >> 3, h = bh & 7;
    int n0 = blockIdx.x * 128;   // K rows (logits cols)
    int m0 = blockIdx.y * 128;   // Q rows (logits rows)
    int wr = wid & 3, wc = wid >> 2;

    const __nv_bfloat16* Aph = Qh + ((size_t)(b * NN + m0)) * DD + h * HD;
    const __nv_bfloat16* Apl = Ql + ((size_t)(b * NN + m0)) * DD + h * HD;
    const __nv_bfloat16* Bph = Kh + ((size_t)(b * NN + n0)) * DD + h * HD;
    const __nv_bfloat16* Bpl = Kl + ((size_t)(b * NN + n0)) * DD + h * HD;

    float acc[2][8][4];
    #pragma unroll
    for (int i = 0; i < 2; i++)
        #pragma unroll
        for (int j = 0; j < 8; j++)
            #pragma unroll
            for (int q = 0; q < 4; q++) acc[i][j][q] = 0.f;

    int r0 = tid >> 2, c0 = (tid & 3) * 8;
    int r1 = r0 + 64;
    uint32_t off0 = (uint32_t)(r0 * LDA + c0) * 2;
    uint32_t off1 = (uint32_t)(r1 * LDA + c0) * 2;

    auto load_stage = [&](int s, int buf) {
        int k0 = s * 32;
        uint32_t bb = sbase + buf * BUFB;
        cpa16(bb             + off0, Aph + (size_t)r0 * DD + k0 + c0);
        cpa16(bb             + off1, Aph + (size_t)r1 * DD + k0 + c0);
        cpa16(bb + TILEB     + off0, Apl + (size_t)r0 * DD + k0 + c0);
        cpa16(bb + TILEB     + off1, Apl + (size_t)r1 * DD + k0 + c0);
        cpa16(bb + 2 * TILEB + off0, Bph + (size_t)r0 * DD + k0 + c0);
        cpa16(bb + 2 * TILEB + off1, Bph + (size_t)r1 * DD + k0 + c0);
        cpa16(bb + 3 * TILEB + off0, Bpl + (size_t)r0 * DD + k0 + c0);
        cpa16(bb + 3 * TILEB + off1, Bpl + (size_t)r1 * DD + k0 + c0);
    };

    load_stage(0, 0);
    cpa_commit();

    uint32_t a_off[2], b_off[4];
    #pragma unroll
    for (int mt = 0; mt < 2; mt++) {
        int row = wr * 32 + mt * 16 + (lane & 15);
        a_off[mt] = (uint32_t)(row * LDA + (lane >> 4) * 8) * 2;
    }
    #pragma unroll
    for (int nt = 0; nt < 4; nt++) {
        int nrow = wc * 64 + nt * 16 + (lane & 7) + ((lane >> 4) & 1) * 8;
        b_off[nt] = (uint32_t)(nrow * LDA + ((lane >> 3) & 1) * 8) * 2;
    }

    #pragma unroll
    for (int s = 0; s < 2; s++) {
        int buf = s & 1;
        if (s == 0) { load_stage(1, 1); cpa_commit(); cpa_wait<1>(); }
        else        { cpa_wait<0>(); }
        __syncthreads();

        uint32_t ah = sbase + buf * BUFB;
        uint32_t al = ah + TILEB;
        uint32_t bh2 = ah + 2 * TILEB;
        uint32_t bl = ah + 3 * TILEB;
        #pragma unroll
        for (int kk = 0; kk < 2; kk++) {
            uint32_t afh[2][4], afl[2][4];
            #pragma unroll
            for (int mt = 0; mt < 2; mt++) {
                ldsm4(afh[mt], ah + a_off[mt] + kk * 32);
                ldsm4(afl[mt], al + a_off[mt] + kk * 32);
            }
            #pragma unroll
            for (int nt = 0; nt < 4; nt++) {
                uint32_t bfh[4], bfl[4];
                ldsm4(bfh, bh2 + b_off[nt] + kk * 32);
                ldsm4(bfl, bl + b_off[nt] + kk * 32);
                #pragma unroll
                for (int mt = 0; mt < 2; mt++) {
                    mma16816(acc[mt][nt * 2 + 0], afh[mt], bfh + 0);
                    mma16816(acc[mt][nt * 2 + 1], afh[mt], bfh + 2);
                    mma16816(acc[mt][nt * 2 + 0], afl[mt], bfh + 0);
                    mma16816(acc[mt][nt * 2 + 1], afl[mt], bfh + 2);
                    mma16816(acc[mt][nt * 2 + 0], afh[mt], bfl + 0);
                    mma16816(acc[mt][nt * 2 + 1], afh[mt], bfl + 2);
                }
            }
        }
        __syncthreads();
    }

    float* lbase = logits + (size_t)bh * NN * NN;
    int gr = lane >> 2, tg = lane & 3;
    #pragma unroll
    for (int mt = 0; mt < 2; mt++) {
        int rbase = m0 + wr * 32 + mt * 16 + gr;
        #pragma unroll
        for (int j = 0; j < 8; j++) {
            int col = n0 + wc * 64 + j * 8 + tg * 2;
            #pragma unroll
            for (int half = 0; half < 2; half++) {
                int row = rbase + half * 8;
                float2 o;
                o.x = acc[mt][j][half * 2 + 0] * 0.125f + rel[(col + 0 - row + MSL - 1) * HH + h];
                o.y = acc[mt][j][half * 2 + 1] * 0.125f + rel[(col + 1 - row + MSL - 1) * HH + h];
                *(float2*)(lbase + (size_t)row * NN + col) = o;
            }
        }
    }
}

// ---------------- weight transpose + fp32 -> bf16 hi/lo ---------------------
__global__ void __launch_bounds__(256) wconv(
    const float* __restrict__ w, __nv_bfloat16* __restrict__ wth,
    __nv_bfloat16* __restrict__ wtl, int Kd, int Nd)
{
    __shared__ float t[32][33];
    int k0 = blockIdx.x * 32, n0 = blockIdx.y * 32;
    int tx = threadIdx.x & 31, ty = threadIdx.x >> 5;   // 32 x 8
    #pragma unroll
    for (int i = 0; i < 4; i++)
        t[ty + 8 * i][tx] = w[(size_t)(k0 + ty + 8 * i) * Nd + n0 + tx];
    __syncthreads();
    #pragma unroll
    for (int i = 0; i < 4; i++) {
        float v = t[tx][ty + 8 * i];
        __nv_bfloat16 h = __float2bfloat16(v);
        size_t o = (size_t)(n0 + ty + 8 * i) * Kd + k0 + tx;
        wth[o] = h;
        wtl[o] = __float2bfloat16(v - __bfloat162float(h));
    }
}

// ---------------- LayerNorm -> bf16 hi/lo ------------------------------------
__global__ void __launch_bounds__(256) ln_kernel(
    const float* __restrict__ x, const float* __restrict__ g,
    const float* __restrict__ be, __nv_bfloat16* __restrict__ oh,
    __nv_bfloat16* __restrict__ ol)
{
    int row = blockIdx.x;
    const float* xr = x + (size_t)row * DD;
    int t = threadIdx.x;
    float v0 = xr[t], v1 = xr[t + 256];
    float s = v0 + v1, ss = v0 * v0 + v1 * v1;
    #pragma unroll
    for (int o = 16; o; o >>= 1) {
        s  += __shfl_xor_sync(0xFFFFFFFFu, s,  o);
        ss += __shfl_xor_sync(0xFFFFFFFFu, ss, o);
    }
    __shared__ float red0[8], red1[8];
    __shared__ float smean, srstd;
    int wid = t >> 5, lane = t & 31;
    if (lane == 0) { red0[wid] = s; red1[wid] = ss; }
    __syncthreads();
    if (t == 0) {
        float a = 0.f, b2 = 0.f;
        #pragma unroll
        for (int i = 0; i < 8; i++) { a += red0[i]; b2 += red1[i]; }
        float mean = a * (1.0f / DD);
        float var  = b2 * (1.0f / DD) - mean * mean;
        smean = mean;
        srstd = rsqrtf(var + 1e-5f);
    }
    __syncthreads();
    float m = smean, r = srstd;
    float y0 = (v0 - m) * r * g[t]       + be[t];
    float y1 = (v1 - m) * r * g[t + 256] + be[t + 256];
    __nv_bfloat16 h0 = __float2bfloat16(y0);
    __nv_bfloat16 h1 = __float2bfloat16(y1);
    size_t o0 = (size_t)row * DD + t;
    oh[o0]       = h0;
    oh[o0 + 256] = h1;
    ol[o0]       = __float2bfloat16(y0 - __bfloat162float(h0));
    ol[o0 + 256] = __float2bfloat16(y1 - __bfloat162float(h1));
}

// ---------------- top-16 + softmax + sparse A*V -> bf16 hi/lo ---------------
__global__ void __launch_bounds__(256) topk_kernel(
    const float* __restrict__ logits, const float* __restrict__ v,
    __nv_bfloat16* __restrict__ ah, __nv_bfloat16* __restrict__ al)
{
    int w = (blockIdx.x * blockDim.x + threadIdx.x) >> 5;   // row id, 0..65535
    int lane = threadIdx.x & 31;
    int n = w & (NN - 1);
    int h = (w >> 9) & 7;
    int b = w >> 12;

    const float* lrow = logits + (size_t)w * NN;
    float vals[16];
    #pragma unroll
    for (int t = 0; t < 16; t++) vals[t] = lrow[t * 32 + lane];

    unsigned mask = 0xFFFFu;
    float selv = 0.f;
    int   selm = 0;
    #pragma unroll
    for (int r = 0; r < 16; r++) {
        float bv = -INFINITY; int bs = 0;
        #pragma unroll
        for (int t = 0; t < 16; t++) {
            bool live = (mask >> t) & 1u;
            if (live && vals[t] > bv) { bv = vals[t]; bs = t; }
        }
        float rv = bv;
        int rm = bs * 32 + lane;
        #pragma unroll
        for (int off = 16; off; off >>= 1) {
            float ov = __shfl_xor_sync(0xFFFFFFFFu, rv, off);
            int   om = __shfl_xor_sync(0xFFFFFFFFu, rm, off);
            if (ov > rv || (ov == rv && om < rm)) { rv = ov; rm = om; }
        }
        if ((rm & 31) == lane) mask &= ~(1u << (rm >> 5));
        if (lane == r) { selv = rv; selm = rm; }
    }

    float maxv = __shfl_sync(0xFFFFFFFFu, selv, 0);
    float e = (lane < 16) ? expf(selv - maxv) : 0.f;
    float s = e;
    #pragma unroll
    for (int off = 16; off; off >>= 1) s += __shfl_xor_sync(0xFFFFFFFFu, s, off);
    float p = e / s;

    float o0 = 0.f, o1 = 0.f;
    const float* vbase = v + ((size_t)b * NN) * DD + h * HD;
    #pragma unroll
    for (int l = 0; l < 16; l++) {
        float pl = __shfl_sync(0xFFFFFFFFu, p, l);
        int   ml = __shfl_sync(0xFFFFFFFFu, selm, l);
        const float* vr = vbase + (size_t)ml * DD;
        o0 += pl * vr[lane];
        o1 += pl * vr[lane + 32];
    }
    size_t base = ((size_t)(b * NN + n)) * DD + h * HD;
    __nv_bfloat16 h0 = __float2bfloat16(o0);
    __nv_bfloat16 h1 = __float2bfloat16(o1);
    ah[base + lane]      = h0;
    ah[base + lane + 32] = h1;
    al[base + lane]      = __float2bfloat16(o0 - __bfloat162float(h0));
    al[base + lane + 32] = __float2bfloat16(o1 - __bfloat162float(h1));
}

// ---------------------------------------------------------------------------
extern "C" void kernel_launch(void* const* d_in, const int* in_sizes, int n_in,
                              void* d_out, int out_size)
{
    const float* x   = (const float*)d_in[0];
    const float* wq  = (const float*)d_in[1];
    const float* bq  = (const float*)d_in[2];
    const float* wk  = (const float*)d_in[3];
    const float* bk  = (const float*)d_in[4];
    const float* wv  = (const float*)d_in[5];
    const float* bv  = (const float*)d_in[6];
    const float* wo  = (const float*)d_in[7];
    const float* bo  = (const float*)d_in[8];
    const float* g1  = (const float*)d_in[9];
    const float* be1 = (const float*)d_in[10];
    const float* g2  = (const float*)d_in[11];
    const float* be2 = (const float*)d_in[12];
    const float* w1  = (const float*)d_in[13];
    const float* bf1 = (const float*)d_in[14];
    const float* w2  = (const float*)d_in[15];
    const float* bf2 = (const float*)d_in[16];
    const float* rel = (const float*)d_in[17];
    float* out = (float*)d_out;

    float *v, *logits, *x1;
    __nv_bfloat16 *qh, *ql, *kh, *kl;
    __nv_bfloat16 *xnh, *xnl, *xn2h, *xn2l, *ath, *atl, *ffh, *ffl;
    __nv_bfloat16 *wqh, *wql, *wkh, *wkl, *wvh, *wvl, *woh, *wol, *w1h, *w1l, *w2h, *w2l;
    cudaGetSymbolAddress((void**)&v,      g_v);
    cudaGetSymbolAddress((void**)&logits, g_logits);
    cudaGetSymbolAddress((void**)&x1,     g_x1);
    cudaGetSymbolAddress((void**)&qh,     g_qb_h);
    cudaGetSymbolAddress((void**)&ql,     g_qb_l);
    cudaGetSymbolAddress((void**)&kh,     g_kb_h);
    cudaGetSymbolAddress((void**)&kl,     g_kb_l);
    cudaGetSymbolAddress((void**)&xnh,    g_xnb_h);
    cudaGetSymbolAddress((void**)&xnl,    g_xnb_l);
    cudaGetSymbolAddress((void**)&xn2h,   g_xn2b_h);
    cudaGetSymbolAddress((void**)&xn2l,   g_xn2b_l);
    cudaGetSymbolAddress((void**)&ath,    g_attnb_h);
    cudaGetSymbolAddress((void**)&atl,    g_attnb_l);
    cudaGetSymbolAddress((void**)&ffh,    g_ffb_h);
    cudaGetSymbolAddress((void**)&ffl,    g_ffb_l);
    cudaGetSymbolAddress((void**)&wqh,    g_wtq_h);
    cudaGetSymbolAddress((void**)&wql,    g_wtq_l);
    cudaGetSymbolAddress((void**)&wkh,    g_wtk_h);
    cudaGetSymbolAddress((void**)&wkl,    g_wtk_l);
    cudaGetSymbolAddress((void**)&wvh,    g_wtv_h);
    cudaGetSymbolAddress((void**)&wvl,    g_wtv_l);
    cudaGetSymbolAddress((void**)&woh,    g_wto_h);
    cudaGetSymbolAddress((void**)&wol,    g_wto_l);
    cudaGetSymbolAddress((void**)&w1h,    g_wt1_h);
    cudaGetSymbolAddress((void**)&w1l,    g_wt1_l);
    cudaGetSymbolAddress((void**)&w2h,    g_wt2_h);
    cudaGetSymbolAddress((void**)&w2l,    g_wt2_l);

    const int SMEM_GEMM = 2 * BUFB;   // 81920
    cudaFuncSetAttribute(gemm_mma<0>, cudaFuncAttributeMaxDynamicSharedMemorySize, SMEM_GEMM);
    cudaFuncSetAttribute(gemm_mma<1>, cudaFuncAttributeMaxDynamicSharedMemorySize, SMEM_GEMM);
    cudaFuncSetAttribute(gemm_mma<2>, cudaFuncAttributeMaxDynamicSharedMemorySize, SMEM_GEMM);
    cudaFuncSetAttribute(gemm_mma<3>, cudaFuncAttributeMaxDynamicSharedMemorySize, SMEM_GEMM);
    cudaFuncSetAttribute(logits_mma,  cudaFuncAttributeMaxDynamicSharedMemorySize, SMEM_GEMM);

    // weight transpose + hi/lo convert
    wconv<<<dim3(DD / 32, DD / 32),  256>>>(wq, wqh, wql, DD, DD);
    wconv<<<dim3(DD / 32, DD / 32),  256>>>(wk, wkh, wkl, DD, DD);
    wconv<<<dim3(DD / 32, DD / 32),  256>>>(wv, wvh, wvl, DD, DD);
    wconv<<<dim3(DD / 32, DD / 32),  256>>>(wo, woh, wol, DD, DD);
    wconv<<<dim3(DD / 32, DFF / 32), 256>>>(w1, w1h, w1l, DD, DFF);
    wconv<<<dim3(DFF / 32, DD / 32), 256>>>(w2, w2h, w2l, DFF, DD);

    dim3 gD(DD / 128, ROWS / 128);      // 4 x 64
    dim3 gF(DFF / 128, ROWS / 128);     // 16 x 64

    // 1. LN1 -> bf16 hi/lo
    ln_kernel<<<ROWS, 256>>>(x, g1, be1, xnh, xnl);
    // 2. Q,K -> bf16 hi/lo; V -> fp32
    gemm_mma<3><<<gD, 256, SMEM_GEMM>>>(xnh, xnl, wqh, wql, bq, nullptr, qh, ql, ROWS, DD, DD);
    gemm_mma<3><<<gD, 256, SMEM_GEMM>>>(xnh, xnl, wkh, wkl, bk, nullptr, kh, kl, ROWS, DD, DD);
    gemm_mma<0><<<gD, 256, SMEM_GEMM>>>(xnh, xnl, wvh, wvl, bv, nullptr, v, nullptr, ROWS, DD, DD);
    // 3. logits + relative bias (bf16x3 HMMA)
    logits_mma<<<dim3(NN / 128, NN / 128, BB * HH), 256, SMEM_GEMM>>>(qh, ql, kh, kl, rel, logits);
    // 4. top-16 -> softmax -> sparse A*V -> bf16 hi/lo
    topk_kernel<<<(BB * HH * NN * 32) / 256, 256>>>(logits, v, ath, atl);
    // 5. output projection + residual
    gemm_mma<1><<<gD, 256, SMEM_GEMM>>>(ath, atl, woh, wol, bo, x, x1, nullptr, ROWS, DD, DD);
    // 6. LN2 -> bf16 hi/lo
    ln_kernel<<<ROWS, 256>>>(x1, g2, be2, xn2h, xn2l);
    // 7. FFN up + exact GELU -> bf16 hi/lo
    gemm_mma<2><<<gF, 256, SMEM_GEMM>>>(xn2h, xn2l, w1h, w1l, bf1, nullptr, ffh, ffl, ROWS, DFF, DD);
    // 8. FFN down + residual -> output
    gemm_mma<1><<<gD, 256, SMEM_GEMM>>>(ffh, ffl, w2h, w2l, bf2, x1, out, nullptr, ROWS, DD, DFF);
}

// round 9
// speedup vs baseline: 2.0883x; 1.0137x over previous
#include <cuda_runtime.h>
#include <cuda_bf16.h>
#include <math.h>
#include <stdint.h>

#define BB   16
#define NN   512
#define DD   512
#define HH   8
#define KTOP 16
#define HD   64
#define MSL  512
#define ROWS (BB*NN)     // 8192
#define DFF  2048

// ---------------- scratch (static device memory; no allocs allowed) ----------
__device__ float g_v    [ROWS*DD];
__device__ float g_logits[(size_t)BB*HH*NN*NN];   // 134 MB
__device__ float g_x1   [ROWS*DD];

__device__ __nv_bfloat16 g_qb_h  [ROWS*DD];
__device__ __nv_bfloat16 g_qb_l  [ROWS*DD];
__device__ __nv_bfloat16 g_kb_h  [ROWS*DD];
__device__ __nv_bfloat16 g_kb_l  [ROWS*DD];
__device__ __nv_bfloat16 g_xnb_h  [ROWS*DD];
__device__ __nv_bfloat16 g_xnb_l  [ROWS*DD];
__device__ __nv_bfloat16 g_xn2b_h [ROWS*DD];
__device__ __nv_bfloat16 g_xn2b_l [ROWS*DD];
__device__ __nv_bfloat16 g_attnb_h[ROWS*DD];
__device__ __nv_bfloat16 g_attnb_l[ROWS*DD];
__device__ __nv_bfloat16 g_ffb_h  [(size_t)ROWS*DFF];
__device__ __nv_bfloat16 g_ffb_l  [(size_t)ROWS*DFF];
__device__ __nv_bfloat16 g_wqkv_h [3*DD*DD];      // packed Q|K|V, [1536][512]
__device__ __nv_bfloat16 g_wqkv_l [3*DD*DD];
__device__ __nv_bfloat16 g_wto_h  [DD*DD];
__device__ __nv_bfloat16 g_wto_l  [DD*DD];
__device__ __nv_bfloat16 g_wt1_h  [(size_t)DD*DFF];
__device__ __nv_bfloat16 g_wt1_l  [(size_t)DD*DFF];
__device__ __nv_bfloat16 g_wt2_h  [(size_t)DFF*DD];
__device__ __nv_bfloat16 g_wt2_l  [(size_t)DFF*DD];

// ================= PTX helpers (base sm_103 target legal) ====================
__device__ __forceinline__ uint32_t smem_u32(const void* p) {
    uint32_t a;
    asm("{ .reg .u64 t; cvta.to.shared.u64 t, %1; cvt.u32.u64 %0, t; }" : "=r"(a) : "l"(p));
    return a;
}
__device__ __forceinline__ void cpa16(uint32_t dst, const void* src) {
    asm volatile("cp.async.cg.shared.global [%0], [%1], 16;" :: "r"(dst), "l"(src));
}
__device__ __forceinline__ void cpa_commit() {
    asm volatile("cp.async.commit_group;" ::: "memory");
}
template<int N>
__device__ __forceinline__ void cpa_wait() {
    asm volatile("cp.async.wait_group %0;" :: "n"(N) : "memory");
}
__device__ __forceinline__ void ldsm4(uint32_t* r, uint32_t addr) {
    asm volatile("ldmatrix.sync.aligned.m8n8.x4.shared.b16 {%0,%1,%2,%3}, [%4];"
                 : "=r"(r[0]), "=r"(r[1]), "=r"(r[2]), "=r"(r[3]) : "r"(addr));
}
__device__ __forceinline__ void mma16816(float* c, const uint32_t* a, const uint32_t* b) {
    asm volatile(
        "mma.sync.aligned.m16n8k16.row.col.f32.bf16.bf16.f32 "
        "{%0,%1,%2,%3}, {%4,%5,%6,%7}, {%8,%9}, {%0,%1,%2,%3};"
        : "+f"(c[0]), "+f"(c[1]), "+f"(c[2]), "+f"(c[3])
        : "r"(a[0]), "r"(a[1]), "r"(a[2]), "r"(a[3]), "r"(b[0]), "r"(b[1]));
}

#define LDA 40                         // padded smem row (elements)
#define TILEB (128 * LDA * 2)          // 10240 bytes per tile
#define BUFB  (4 * TILEB)              // Ah,Al,Bh,Bl per buffer

// ======= shared mainloop: bf16x3 triple-mma over K, double-buffered =========
// acc += Ah*Bh + Al*Bh + Ah*Bl
#define GEMM_CORE(APH, APL, BPH, BPL, STRIDE, SCOUNT)                          \
    int r0 = tid >> 2, c0 = (tid & 3) * 8;                                     \
    int r1 = r0 + 64;                                                          \
    uint32_t off0 = (uint32_t)(r0 * LDA + c0) * 2;                             \
    uint32_t off1 = (uint32_t)(r1 * LDA + c0) * 2;                             \
    auto load_stage = [&](int s, int buf) {                                    \
        int k0 = s * 32;                                                       \
        uint32_t b = sbase + buf * BUFB;                                       \
        cpa16(b             + off0, APH + (size_t)r0 * STRIDE + k0 + c0);      \
        cpa16(b             + off1, APH + (size_t)r1 * STRIDE + k0 + c0);      \
        cpa16(b + TILEB     + off0, APL + (size_t)r0 * STRIDE + k0 + c0);      \
        cpa16(b + TILEB     + off1, APL + (size_t)r1 * STRIDE + k0 + c0);      \
        cpa16(b + 2 * TILEB + off0, BPH + (size_t)r0 * STRIDE + k0 + c0);      \
        cpa16(b + 2 * TILEB + off1, BPH + (size_t)r1 * STRIDE + k0 + c0);      \
        cpa16(b + 3 * TILEB + off0, BPL + (size_t)r0 * STRIDE + k0 + c0);      \
        cpa16(b + 3 * TILEB + off1, BPL + (size_t)r1 * STRIDE + k0 + c0);      \
    };                                                                         \
    load_stage(0, 0);                                                          \
    cpa_commit();                                                              \
    uint32_t a_off[2], b_off[4];                                               \
    _Pragma("unroll")                                                          \
    for (int mt = 0; mt < 2; mt++) {                                           \
        int row = wr * 32 + mt * 16 + (lane & 15);                             \
        a_off[mt] = (uint32_t)(row * LDA + (lane >> 4) * 8) * 2;               \
    }                                                                          \
    _Pragma("unroll")                                                          \
    for (int nt = 0; nt < 4; nt++) {                                           \
        int nrow = wc * 64 + nt * 16 + (lane & 7) + ((lane >> 4) & 1) * 8;     \
        b_off[nt] = (uint32_t)(nrow * LDA + ((lane >> 3) & 1) * 8) * 2;        \
    }                                                                          \
    for (int s = 0; s < SCOUNT; s++) {                                         \
        int buf = s & 1;                                                       \
        if (s + 1 < SCOUNT) { load_stage(s + 1, buf ^ 1); cpa_commit(); cpa_wait<1>(); } \
        else               { cpa_wait<0>(); }                                  \
        __syncthreads();                                                       \
        uint32_t ah = sbase + buf * BUFB;                                      \
        uint32_t al = ah + TILEB;                                              \
        uint32_t bh = ah + 2 * TILEB;                                          \
        uint32_t bl = ah + 3 * TILEB;                                          \
        _Pragma("unroll")                                                      \
        for (int kk = 0; kk < 2; kk++) {                                       \
            uint32_t afh[2][4], afl[2][4];                                     \
            _Pragma("unroll")                                                  \
            for (int mt = 0; mt < 2; mt++) {                                   \
                ldsm4(afh[mt], ah + a_off[mt] + kk * 32);                      \
                ldsm4(afl[mt], al + a_off[mt] + kk * 32);                      \
            }                                                                  \
            _Pragma("unroll")                                                  \
            for (int nt = 0; nt < 4; nt++) {                                   \
                uint32_t bfh[4], bfl[4];                                       \
                ldsm4(bfh, bh + b_off[nt] + kk * 32);                          \
                ldsm4(bfl, bl + b_off[nt] + kk * 32);                          \
                _Pragma("unroll")                                              \
                for (int mt = 0; mt < 2; mt++) {                               \
                    mma16816(acc[mt][nt * 2 + 0], afh[mt], bfh + 0);           \
                    mma16816(acc[mt][nt * 2 + 1], afh[mt], bfh + 2);           \
                    mma16816(acc[mt][nt * 2 + 0], afl[mt], bfh + 0);           \
                    mma16816(acc[mt][nt * 2 + 1], afl[mt], bfh + 2);           \
                    mma16816(acc[mt][nt * 2 + 0], afh[mt], bfl + 0);           \
                    mma16816(acc[mt][nt * 2 + 1], afh[mt], bfl + 2);           \
                }                                                              \
            }                                                                  \
        }                                                                      \
        __syncthreads();                                                       \
    }

#define ACC_INIT                                                               \
    float acc[2][8][4];                                                        \
    _Pragma("unroll")                                                          \
    for (int i = 0; i < 2; i++)                                                \
        _Pragma("unroll")                                                      \
        for (int j = 0; j < 8; j++)                                            \
            _Pragma("unroll")                                                  \
            for (int q = 0; q < 4; q++) acc[i][j][q] = 0.f;

// ================= generic GEMM, 128x128 tile ===============================
// MODE 1: C(fp32) = acc + bias + res
// MODE 2: hi/lo bf16 = gelu(acc + bias)
template<int MODE>
__global__ void __launch_bounds__(256, 2) gemm_mma(
    const __nv_bfloat16* __restrict__ Ah, const __nv_bfloat16* __restrict__ Al,
    const __nv_bfloat16* __restrict__ Bh, const __nv_bfloat16* __restrict__ Bl,
    const float* __restrict__ bias, const float* __restrict__ res,
    void* __restrict__ Cout, void* __restrict__ Cout2, int M, int N, int Kd)
{
    extern __shared__ char smem[];
    uint32_t sbase = smem_u32(smem);
    int tid = threadIdx.x, wid = tid >> 5, lane = tid & 31;
    int n0 = blockIdx.x * 128, m0 = blockIdx.y * 128;
    int wr = wid & 3, wc = wid >> 2;

    const __nv_bfloat16* Aph = Ah + (size_t)m0 * Kd;
    const __nv_bfloat16* Apl = Al + (size_t)m0 * Kd;
    const __nv_bfloat16* Bph = Bh + (size_t)n0 * Kd;
    const __nv_bfloat16* Bpl = Bl + (size_t)n0 * Kd;

    ACC_INIT;
    int S = Kd >> 5;
    GEMM_CORE(Aph, Apl, Bph, Bpl, Kd, S);

    int gr = lane >> 2, tg = lane & 3;
    #pragma unroll
    for (int mt = 0; mt < 2; mt++) {
        int rbase = m0 + wr * 32 + mt * 16 + gr;
        #pragma unroll
        for (int j = 0; j < 8; j++) {
            int col = n0 + wc * 64 + j * 8 + tg * 2;
            #pragma unroll
            for (int half = 0; half < 2; half++) {
                int row = rbase + half * 8;
                float v0 = acc[mt][j][half * 2 + 0] + bias[col];
                float v1 = acc[mt][j][half * 2 + 1] + bias[col + 1];
                if (MODE == 2) {
                    v0 = 0.5f * v0 * (1.0f + erff(v0 * 0.70710678118654752f));
                    v1 = 0.5f * v1 * (1.0f + erff(v1 * 0.70710678118654752f));
                    __nv_bfloat162 ph, pl;
                    ph.x = __float2bfloat16(v0);
                    ph.y = __float2bfloat16(v1);
                    pl.x = __float2bfloat16(v0 - __bfloat162float(ph.x));
                    pl.y = __float2bfloat16(v1 - __bfloat162float(ph.y));
                    *(__nv_bfloat162*)((__nv_bfloat16*)Cout  + (size_t)row * N + col) = ph;
                    *(__nv_bfloat162*)((__nv_bfloat16*)Cout2 + (size_t)row * N + col) = pl;
                } else {
                    const float* rr = res + (size_t)row * N + col;
                    float2 o; o.x = v0 + rr[0]; o.y = v1 + rr[1];
                    *(float2*)((float*)Cout + (size_t)row * N + col) = o;
                }
            }
        }
    }
}

// ================= fused QKV GEMM: N=1536 packed, mixed epilogue ============
__global__ void __launch_bounds__(256, 2) gemm_qkv(
    const __nv_bfloat16* __restrict__ Ah, const __nv_bfloat16* __restrict__ Al,
    const __nv_bfloat16* __restrict__ Bh, const __nv_bfloat16* __restrict__ Bl,
    const float* __restrict__ bq, const float* __restrict__ bk,
    const float* __restrict__ bv,
    __nv_bfloat16* __restrict__ qh, __nv_bfloat16* __restrict__ ql,
    __nv_bfloat16* __restrict__ kh, __nv_bfloat16* __restrict__ kl,
    float* __restrict__ v)
{
    extern __shared__ char smem[];
    uint32_t sbase = smem_u32(smem);
    int tid = threadIdx.x, wid = tid >> 5, lane = tid & 31;
    int n0 = blockIdx.x * 128, m0 = blockIdx.y * 128;
    int wr = wid & 3, wc = wid >> 2;

    const __nv_bfloat16* Aph = Ah + (size_t)m0 * DD;
    const __nv_bfloat16* Apl = Al + (size_t)m0 * DD;
    const __nv_bfloat16* Bph = Bh + (size_t)n0 * DD;
    const __nv_bfloat16* Bpl = Bl + (size_t)n0 * DD;

    ACC_INIT;
    GEMM_CORE(Aph, Apl, Bph, Bpl, DD, 16);

    // epilogue: n0 in [0,512) -> Q hi/lo, [512,1024) -> K hi/lo, else V fp32
    int gr = lane >> 2, tg = lane & 3;
    int sel = n0 >> 9;                       // 0=Q, 1=K, 2=V
    const float* bias = (sel == 0) ? bq : (sel == 1) ? bk : bv;
    __nv_bfloat16* oh = (sel == 0) ? qh : kh;
    __nv_bfloat16* ol = (sel == 0) ? ql : kl;
    int nloc = n0 & 511;
    #pragma unroll
    for (int mt = 0; mt < 2; mt++) {
        int rbase = m0 + wr * 32 + mt * 16 + gr;
        #pragma unroll
        for (int j = 0; j < 8; j++) {
            int col = nloc + wc * 64 + j * 8 + tg * 2;
            #pragma unroll
            for (int half = 0; half < 2; half++) {
                int row = rbase + half * 8;
                float v0 = acc[mt][j][half * 2 + 0] + bias[col];
                float v1 = acc[mt][j][half * 2 + 1] + bias[col + 1];
                if (sel == 2) {
                    float2 o; o.x = v0; o.y = v1;
                    *(float2*)(v + (size_t)row * DD + col) = o;
                } else {
                    __nv_bfloat162 ph, pl;
                    ph.x = __float2bfloat16(v0);
                    ph.y = __float2bfloat16(v1);
                    pl.x = __float2bfloat16(v0 - __bfloat162float(ph.x));
                    pl.y = __float2bfloat16(v1 - __bfloat162float(ph.y));
                    *(__nv_bfloat162*)(oh + (size_t)row * DD + col) = ph;
                    *(__nv_bfloat162*)(ol + (size_t)row * DD + col) = pl;
                }
            }
        }
    }
}

// ============ logits: bf16x3 HMMA, per (b,h), 128x128 tile, Kd=64 ===========
__global__ void __launch_bounds__(256, 2) logits_mma(
    const __nv_bfloat16* __restrict__ Qh, const __nv_bfloat16* __restrict__ Ql,
    const __nv_bfloat16* __restrict__ Kh, const __nv_bfloat16* __restrict__ Kl,
    const float* __restrict__ rel, float* __restrict__ logits)
{
    extern __shared__ char smem[];
    uint32_t sbase = smem_u32(smem);
    int tid = threadIdx.x, wid = tid >> 5, lane = tid & 31;
    int bh2 = blockIdx.z;
    int b = bh2 >> 3, h = bh2 & 7;
    int n0 = blockIdx.x * 128;
    int m0 = blockIdx.y * 128;
    int wr = wid & 3, wc = wid >> 2;

    const __nv_bfloat16* Aph = Qh + ((size_t)(b * NN + m0)) * DD + h * HD;
    const __nv_bfloat16* Apl = Ql + ((size_t)(b * NN + m0)) * DD + h * HD;
    const __nv_bfloat16* Bph = Kh + ((size_t)(b * NN + n0)) * DD + h * HD;
    const __nv_bfloat16* Bpl = Kl + ((size_t)(b * NN + n0)) * DD + h * HD;

    ACC_INIT;
    GEMM_CORE(Aph, Apl, Bph, Bpl, DD, 2);

    float* lbase = logits + (size_t)bh2 * NN * NN;
    int gr = lane >> 2, tg = lane & 3;
    #pragma unroll
    for (int mt = 0; mt < 2; mt++) {
        int rbase = m0 + wr * 32 + mt * 16 + gr;
        #pragma unroll
        for (int j = 0; j < 8; j++) {
            int col = n0 + wc * 64 + j * 8 + tg * 2;
            #pragma unroll
            for (int half = 0; half < 2; half++) {
                int row = rbase + half * 8;
                float2 o;
                o.x = acc[mt][j][half * 2 + 0] * 0.125f + rel[(col + 0 - row + MSL - 1) * HH + h];
                o.y = acc[mt][j][half * 2 + 1] * 0.125f + rel[(col + 1 - row + MSL - 1) * HH + h];
                *(float2*)(lbase + (size_t)row * NN + col) = o;
            }
        }
    }
}

// ---------------- weight transpose + fp32 -> bf16 hi/lo ---------------------
__global__ void __launch_bounds__(256) wconv(
    const float* __restrict__ w, __nv_bfloat16* __restrict__ wth,
    __nv_bfloat16* __restrict__ wtl, int Kd, int Nd)
{
    __shared__ float t[32][33];
    int k0 = blockIdx.x * 32, n0 = blockIdx.y * 32;
    int tx = threadIdx.x & 31, ty = threadIdx.x >> 5;
    #pragma unroll
    for (int i = 0; i < 4; i++)
        t[ty + 8 * i][tx] = w[(size_t)(k0 + ty + 8 * i) * Nd + n0 + tx];
    __syncthreads();
    #pragma unroll
    for (int i = 0; i < 4; i++) {
        float v = t[tx][ty + 8 * i];
        __nv_bfloat16 h = __float2bfloat16(v);
        size_t o = (size_t)(n0 + ty + 8 * i) * Kd + k0 + tx;
        wth[o] = h;
        wtl[o] = __float2bfloat16(v - __bfloat162float(h));
    }
}

// ---------------- LayerNorm -> bf16 hi/lo ------------------------------------
__global__ void __launch_bounds__(256) ln_kernel(
    const float* __restrict__ x, const float* __restrict__ g,
    const float* __restrict__ be, __nv_bfloat16* __restrict__ oh,
    __nv_bfloat16* __restrict__ ol)
{
    int row = blockIdx.x;
    const float* xr = x + (size_t)row * DD;
    int t = threadIdx.x;
    float v0 = xr[t], v1 = xr[t + 256];
    float s = v0 + v1, ss = v0 * v0 + v1 * v1;
    #pragma unroll
    for (int o = 16; o; o >>= 1) {
        s  += __shfl_xor_sync(0xFFFFFFFFu, s,  o);
        ss += __shfl_xor_sync(0xFFFFFFFFu, ss, o);
    }
    __shared__ float red0[8], red1[8];
    __shared__ float smean, srstd;
    int wid = t >> 5, lane = t & 31;
    if (lane == 0) { red0[wid] = s; red1[wid] = ss; }
    __syncthreads();
    if (t == 0) {
        float a = 0.f, b2 = 0.f;
        #pragma unroll
        for (int i = 0; i < 8; i++) { a += red0[i]; b2 += red1[i]; }
        float mean = a * (1.0f / DD);
        float var  = b2 * (1.0f / DD) - mean * mean;
        smean = mean;
        srstd = rsqrtf(var + 1e-5f);
    }
    __syncthreads();
    float m = smean, r = srstd;
    float y0 = (v0 - m) * r * g[t]       + be[t];
    float y1 = (v1 - m) * r * g[t + 256] + be[t + 256];
    __nv_bfloat16 h0 = __float2bfloat16(y0);
    __nv_bfloat16 h1 = __float2bfloat16(y1);
    size_t o0 = (size_t)row * DD + t;
    oh[o0]       = h0;
    oh[o0 + 256] = h1;
    ol[o0]       = __float2bfloat16(y0 - __bfloat162float(h0));
    ol[o0 + 256] = __float2bfloat16(y1 - __bfloat162float(h1));
}

// ---------------- top-16 + softmax + sparse A*V -> bf16 hi/lo ---------------
__global__ void __launch_bounds__(256) topk_kernel(
    const float* __restrict__ logits, const float* __restrict__ v,
    __nv_bfloat16* __restrict__ ah, __nv_bfloat16* __restrict__ al)
{
    int w = (blockIdx.x * blockDim.x + threadIdx.x) >> 5;
    int lane = threadIdx.x & 31;
    int n = w & (NN - 1);
    int h = (w >> 9) & 7;
    int b = w >> 12;

    const float* lrow = logits + (size_t)w * NN;
    float vals[16];
    #pragma unroll
    for (int t = 0; t < 16; t++) vals[t] = lrow[t * 32 + lane];

    unsigned mask = 0xFFFFu;
    float selv = 0.f;
    int   selm = 0;
    #pragma unroll
    for (int r = 0; r < 16; r++) {
        float bv = -INFINITY; int bs = 0;
        #pragma unroll
        for (int t = 0; t < 16; t++) {
            bool live = (mask >> t) & 1u;
            if (live && vals[t] > bv) { bv = vals[t]; bs = t; }
        }
        float rv = bv;
        int rm = bs * 32 + lane;
        #pragma unroll
        for (int off = 16; off; off >>= 1) {
            float ov = __shfl_xor_sync(0xFFFFFFFFu, rv, off);
            int   om = __shfl_xor_sync(0xFFFFFFFFu, rm, off);
            if (ov > rv || (ov == rv && om < rm)) { rv = ov; rm = om; }
        }
        if ((rm & 31) == lane) mask &= ~(1u << (rm >> 5));
        if (lane == r) { selv = rv; selm = rm; }
    }

    float maxv = __shfl_sync(0xFFFFFFFFu, selv, 0);
    float e = (lane < 16) ? expf(selv - maxv) : 0.f;
    float s = e;
    #pragma unroll
    for (int off = 16; off; off >>= 1) s += __shfl_xor_sync(0xFFFFFFFFu, s, off);
    float p = e / s;

    float o0 = 0.f, o1 = 0.f;
    const float* vbase = v + ((size_t)b * NN) * DD + h * HD;
    #pragma unroll
    for (int l = 0; l < 16; l++) {
        float pl = __shfl_sync(0xFFFFFFFFu, p, l);
        int   ml = __shfl_sync(0xFFFFFFFFu, selm, l);
        const float* vr = vbase + (size_t)ml * DD;
        o0 += pl * vr[lane];
        o1 += pl * vr[lane + 32];
    }
    size_t base = ((size_t)(b * NN + n)) * DD + h * HD;
    __nv_bfloat16 h0 = __float2bfloat16(o0);
    __nv_bfloat16 h1 = __float2bfloat16(o1);
    ah[base + lane]      = h0;
    ah[base + lane + 32] = h1;
    al[base + lane]      = __float2bfloat16(o0 - __bfloat162float(h0));
    al[base + lane + 32] = __float2bfloat16(o1 - __bfloat162float(h1));
}

// ---------------------------------------------------------------------------
extern "C" void kernel_launch(void* const* d_in, const int* in_sizes, int n_in,
                              void* d_out, int out_size)
{
    const float* x   = (const float*)d_in[0];
    const float* wq  = (const float*)d_in[1];
    const float* bq  = (const float*)d_in[2];
    const float* wk  = (const float*)d_in[3];
    const float* bk  = (const float*)d_in[4];
    const float* wv  = (const float*)d_in[5];
    const float* bv  = (const float*)d_in[6];
    const float* wo  = (const float*)d_in[7];
    const float* bo  = (const float*)d_in[8];
    const float* g1  = (const float*)d_in[9];
    const float* be1 = (const float*)d_in[10];
    const float* g2  = (const float*)d_in[11];
    const float* be2 = (const float*)d_in[12];
    const float* w1  = (const float*)d_in[13];
    const float* bf1 = (const float*)d_in[14];
    const float* w2  = (const float*)d_in[15];
    const float* bf2 = (const float*)d_in[16];
    const float* rel = (const float*)d_in[17];
    float* out = (float*)d_out;

    float *v, *logits, *x1;
    __nv_bfloat16 *qh, *ql, *kh, *kl;
    __nv_bfloat16 *xnh, *xnl, *xn2h, *xn2l, *ath, *atl, *ffh, *ffl;
    __nv_bfloat16 *wqkvh, *wqkvl, *woh, *wol, *w1h, *w1l, *w2h, *w2l;
    cudaGetSymbolAddress((void**)&v,      g_v);
    cudaGetSymbolAddress((void**)&logits, g_logits);
    cudaGetSymbolAddress((void**)&x1,     g_x1);
    cudaGetSymbolAddress((void**)&qh,     g_qb_h);
    cudaGetSymbolAddress((void**)&ql,     g_qb_l);
    cudaGetSymbolAddress((void**)&kh,     g_kb_h);
    cudaGetSymbolAddress((void**)&kl,     g_kb_l);
    cudaGetSymbolAddress((void**)&xnh,    g_xnb_h);
    cudaGetSymbolAddress((void**)&xnl,    g_xnb_l);
    cudaGetSymbolAddress((void**)&xn2h,   g_xn2b_h);
    cudaGetSymbolAddress((void**)&xn2l,   g_xn2b_l);
    cudaGetSymbolAddress((void**)&ath,    g_attnb_h);
    cudaGetSymbolAddress((void**)&atl,    g_attnb_l);
    cudaGetSymbolAddress((void**)&ffh,    g_ffb_h);
    cudaGetSymbolAddress((void**)&ffl,    g_ffb_l);
    cudaGetSymbolAddress((void**)&wqkvh,  g_wqkv_h);
    cudaGetSymbolAddress((void**)&wqkvl,  g_wqkv_l);
    cudaGetSymbolAddress((void**)&woh,    g_wto_h);
    cudaGetSymbolAddress((void**)&wol,    g_wto_l);
    cudaGetSymbolAddress((void**)&w1h,    g_wt1_h);
    cudaGetSymbolAddress((void**)&w1l,    g_wt1_l);
    cudaGetSymbolAddress((void**)&w2h,    g_wt2_h);
    cudaGetSymbolAddress((void**)&w2l,    g_wt2_l);

    const int SMEM_GEMM = 2 * BUFB;   // 81920
    cudaFuncSetAttribute(gemm_mma<1>, cudaFuncAttributeMaxDynamicSharedMemorySize, SMEM_GEMM);
    cudaFuncSetAttribute(gemm_mma<2>, cudaFuncAttributeMaxDynamicSharedMemorySize, SMEM_GEMM);
    cudaFuncSetAttribute(gemm_qkv,    cudaFuncAttributeMaxDynamicSharedMemorySize, SMEM_GEMM);
    cudaFuncSetAttribute(logits_mma,  cudaFuncAttributeMaxDynamicSharedMemorySize, SMEM_GEMM);

    dim3 gD(DD / 128, ROWS / 128);      // 4 x 64
    dim3 gQKV(3 * DD / 128, ROWS / 128);// 12 x 64
    dim3 gF(DFF / 128, ROWS / 128);     // 16 x 64

    // launches 1-4: weight converts (Q|K|V packed rows, then O)
    wconv<<<dim3(DD / 32, DD / 32), 256>>>(wq, wqkvh,               wqkvl,               DD, DD);
    wconv<<<dim3(DD / 32, DD / 32), 256>>>(wk, wqkvh + DD * DD,     wqkvl + DD * DD,     DD, DD);
    wconv<<<dim3(DD / 32, DD / 32), 256>>>(wv, wqkvh + 2 * DD * DD, wqkvl + 2 * DD * DD, DD, DD);
    wconv<<<dim3(DD / 32, DD / 32), 256>>>(wo, woh, wol, DD, DD);
    // launch 5: LN1
    ln_kernel<<<ROWS, 256>>>(x, g1, be1, xnh, xnl);
    // launch 6 (ncu captures this): fused QKV projection
    gemm_qkv<<<gQKV, 256, SMEM_GEMM>>>(xnh, xnl, wqkvh, wqkvl,
                                       bq, bk, bv, qh, ql, kh, kl, v);
    // FFN weight converts (independent; overlap launch gap)
    wconv<<<dim3(DD / 32, DFF / 32), 256>>>(w1, w1h, w1l, DD, DFF);
    wconv<<<dim3(DFF / 32, DD / 32), 256>>>(w2, w2h, w2l, DFF, DD);
    // logits + relative bias
    logits_mma<<<dim3(NN / 128, NN / 128, BB * HH), 256, SMEM_GEMM>>>(qh, ql, kh, kl, rel, logits);
    // top-16 -> softmax -> sparse A*V
    topk_kernel<<<(BB * HH * NN * 32) / 256, 256>>>(logits, v, ath, atl);
    // output projection + residual
    gemm_mma<1><<<gD, 256, SMEM_GEMM>>>(ath, atl, woh, wol, bo, x, x1, nullptr, ROWS, DD, DD);
    // LN2
    ln_kernel<<<ROWS, 256>>>(x1, g2, be2, xn2h, xn2l);
    // FFN up + exact GELU
    gemm_mma<2><<<gF, 256, SMEM_GEMM>>>(xn2h, xn2l, w1h, w1l, bf1, nullptr, ffh, ffl, ROWS, DFF, DD);
    // FFN down + residual -> output
    gemm_mma<1><<<gD, 256, SMEM_GEMM>>>(ffh, ffl, w2h, w2l, bf2, x1, out, nullptr, ROWS, DD, DFF);
}